// round 12
// baseline (speedup 1.0000x reference)
#include <cuda_runtime.h>
#include <math_constants.h>
#include <math.h>

#define BS    16
#define NMAX  64
#define NA    8400
#define NC    80
#define TOPK_ 13
#define EPS   1e-9f
#define CEPS  1e-7f
#define FLT_MIN_NORMAL 1.17549435e-38f
#define P_CAP 320    // in-box candidates <= 15^2+8^2+4^2 = 305
#define B_CAP 320
#define NT1   128
// tscores zero-fill: BS*NA*NC floats = 10,752,000 -> 10,500 floats (2625 float4) per k1 block
#define ZF_F4_PER_BLOCK 2625

// ---------------- persistent scratch (small) ----------------
__device__ unsigned int g_cnt   [BS*NA];     // zero at load; k2 re-zeroes after read
__device__ uint4        g_claim [BS*NA];     // {g, align_bits, overlap_bits, 0}
__device__ float        g_anchor_al[BS*NA];
__device__ unsigned int g_posalign[BS*NMAX]; // float bits (nonneg)
__device__ unsigned int g_posov   [BS*NMAX];

// analytic anchor grid (bitwise-equal to reference's (i+0.5)*s construction)
__device__ __forceinline__ void anchor_decode(int n, float rmscale,
                                              float& ax, float& ay, float& aps) {
    if (n < 6400)      { int r = n / 80;        int c = n - r*80;        ax = (c+0.5f)*8.f;  ay = (r+0.5f)*8.f;  aps = 8.f*rmscale;  }
    else if (n < 8000) { int r = (n-6400) / 40; int c = (n-6400) - r*40; ax = (c+0.5f)*16.f; ay = (r+0.5f)*16.f; aps = 16.f*rmscale; }
    else               { int r = (n-8000) / 20; int c = (n-8000) - r*20; ax = (c+0.5f)*32.f; ay = (r+0.5f)*32.f; aps = 32.f*rmscale; }
}

struct GTC {
    float gx1, gy1, gx2, gy2;
    float w1h1, atan1, gsx, gsy;
    float gt_size, areap, kx, ky;
    float kmask, kden, valid;
    int   lbl;
};

__device__ __forceinline__ void make_gtc(GTC& g, const float* gt_bboxes,
                                         const int* gt_labels, const float* mask_gt,
                                         const float* gt_kkpts, int bg) {
    float gx1 = gt_bboxes[bg*4+0], gy1 = gt_bboxes[bg*4+1];
    float gx2 = gt_bboxes[bg*4+2], gy2 = gt_bboxes[bg*4+3];
    g.gx1 = gx1; g.gy1 = gy1; g.gx2 = gx2; g.gy2 = gy2;
    float w1 = gx2 - gx1, h1 = gy2 - gy1 + CEPS;
    g.atan1 = atanf(w1 / h1);
    g.w1h1  = w1 * h1;
    g.gsx = gx1 + gx2; g.gsy = gy1 + gy2;
    float gw = gx2 - gx1, gh = gy2 - gy1;
    g.gt_size = 0.5f * (gw + gh);
    g.areap   = gw * gh * 0.53f + 1e-7f;
    g.kx = gt_kkpts[bg*3+0]; g.ky = gt_kkpts[bg*3+1];
    float kv = gt_kkpts[bg*3+2];
    g.kmask = (kv != 0.f) ? 1.f : 0.f;
    g.kden  = g.kmask + 1e-7f;
    g.valid = mask_gt[bg];
    g.lbl   = gt_labels[bg];
}

// overlap for an m==1 cell; same arithmetic sequence as all passing rounds
__device__ __forceinline__ float eval_overlap(const GTC& g, float4 box, float atn,
                                              float pkx, float pky, float fs2) {
    const float inv_pi2_4 = 0.4052847345693511f;
    float px1 = box.x, py1 = box.y, px2 = box.z, py2 = box.w;
    float w2 = px2 - px1, h2 = py2 - py1 + CEPS;
    float iw = fminf(g.gx2, px2) - fmaxf(g.gx1, px1);
    float ih = fminf(g.gy2, py2) - fmaxf(g.gy1, py1);
    float inter = fmaxf(iw, 0.f) * fmaxf(ih, 0.f);
    float uni = g.w1h1 + w2 * h2 - inter + CEPS;
    float iou = inter / uni;
    float cw = fmaxf(g.gx2, px2) - fminf(g.gx1, px1);
    float ch = fmaxf(g.gy2, py2) - fminf(g.gy1, py1);
    float c2 = cw*cw + ch*ch + CEPS;
    float dx = px1 + px2 - g.gsx, dy = py1 + py2 - g.gsy;
    float rho2 = (dx*dx + dy*dy) / 4.0f;
    float dat = atn - g.atan1;
    float v = inv_pi2_4 * (dat * dat);
    float a = v / (v - iou + (1.f + CEPS));
    float cio = iou - (rho2 / c2 + v * a);
    cio = fmaxf(cio, 0.f);
    float ddx = pkx - g.kx, ddy = pky - g.ky;
    float d2 = ddx*ddx + ddy*ddy;
    float e = d2 / fs2 / g.areap / 2.0f;
    float kio = (expf(-e) * g.kmask) / g.kden;
    float overlap = (cio + kio) / 2.0f;
    if (overlap < FLT_MIN_NORMAL) overlap = 0.f;   // FTZ (matches reference)
    return overlap;
}

__device__ __forceinline__ float parse_rmf(const int* regmax_p) {
    float rmf = 16.f;
    if (regmax_p) {
        int v = regmax_p[0];
        if (v >= 1 && v <= 65536) rmf = (float)v;
        else { float fv = __int_as_float(v); if (fv >= 1.f && fv <= 65536.f) rmf = fv; }
    }
    return rmf;
}

__device__ __forceinline__ float pd_atan(float4 box) {
    float w2 = box.z - box.x;
    float h2 = box.w - box.y + CEPS;
    return atanf(w2 / h2);
}

// race-safe claim: plain STG.128 + RED.ADD; data only trusted when final cnt==1
__device__ __forceinline__ void emit_claim(size_t idx, int g, float alv, float ov) {
    g_claim[idx] = make_uint4((unsigned)g, __float_as_uint(alv), __float_as_uint(ov), 0u);
    atomicAdd(&g_cnt[idx], 1u);
}

// ---------------- K1: zero-fill tscores slice + build + adaptive top-13 ----------------
__global__ void __launch_bounds__(NT1) k1_metrics(
    const float* __restrict__ pd_scores, const float* __restrict__ pd_bboxes,
    const int* __restrict__ gt_labels,  const float* __restrict__ gt_bboxes,
    const float* __restrict__ mask_gt,  const float* __restrict__ gt_kkpts,
    const float* __restrict__ pd_kkpts, const float* __restrict__ sigma,
    const int* __restrict__ regmax_p,   float* __restrict__ o_tscores)
{
    __shared__ unsigned long long s_pkey[P_CAP];
    __shared__ float s_pov[P_CAP];
    __shared__ int   s_bidx[B_CAP];
    __shared__ float s_bov[B_CAP];
    __shared__ unsigned int s_bm[16];   // 512-bit bitmap (cutoff < 512 provably)
    __shared__ int s_pcnt, s_bcnt;
    __shared__ unsigned long long s_wkey[TOPK_];
    __shared__ float s_wov[TOPK_];

    int bg = blockIdx.x;
    int b  = bg >> 6;
    int g  = bg & 63;
    int tid = threadIdx.x;

    if (tid == 0) { g_posalign[bg] = 0u; g_posov[bg] = 0u; s_pcnt = 0; s_bcnt = 0; }
    if (tid < 16) s_bm[tid] = 0u;

    // ---- zero-fill this block's tscores slice (rides k1's idle store/DRAM-BW) ----
    {
        float4* z = (float4*)o_tscores + (size_t)bg * ZF_F4_PER_BLOCK;
        float4 zv = make_float4(0.f, 0.f, 0.f, 0.f);
        #pragma unroll 3
        for (int i = tid; i < ZF_F4_PER_BLOCK; i += NT1) z[i] = zv;
    }

    float mgt = mask_gt[bg];
    __syncthreads();
    if (mgt == 0.f) return;

    float rmf = parse_rmf(regmax_p);
    float rmscale = (rmf - 1.f) * 2.f;
    float sg = sigma[0];
    float fs2 = (2.f*sg)*(2.f*sg);

    GTC gc; make_gtc(gc, gt_bboxes, gt_labels, mask_gt, gt_kkpts, bg);

    const float4* pb = (const float4*)(pd_bboxes + (size_t)b * NA * 4);
    const float*  ps = pd_scores + (size_t)b * NA * NC + gc.lbl;
    const float*  pk = pd_kkpts  + (size_t)b * NA * 3;

    const int   L_base[3] = {0, 6400, 8000};
    const int   L_W[3]    = {80, 40, 20};
    const float L_s[3]    = {8.f, 16.f, 32.f};

    #pragma unroll
    for (int l = 0; l < 3; l++) {
        float s = L_s[l];
        float aps = s * rmscale;
        if (!((aps - gc.gt_size) >= EPS)) continue;
        int W = L_W[l];
        float inv_s = 1.f / s;
        int c_lo = max(0,     (int)floorf(gc.gx1 * inv_s - 0.5f) - 1);
        int c_hi = min(W - 1, (int)floorf(gc.gx2 * inv_s - 0.5f) + 1);
        int r_lo = max(0,     (int)floorf(gc.gy1 * inv_s - 0.5f) - 1);
        int r_hi = min(W - 1, (int)floorf(gc.gy2 * inv_s - 0.5f) + 1);
        int ncc = c_hi - c_lo + 1, nrr = r_hi - r_lo + 1;
        if (ncc <= 0 || nrr <= 0) continue;
        int tot = ncc * nrr;
        for (int j = tid; j < tot; j += NT1) {
            int r = r_lo + j / ncc, c = c_lo + j % ncc;
            float ax = (c + 0.5f) * s, ay = (r + 0.5f) * s;
            float din = fminf(fminf(ax - gc.gx1, ay - gc.gy1),
                              fminf(gc.gx2 - ax, gc.gy2 - ay));
            if (!(din > EPS)) continue;          // exact in-box test
            int n = L_base[l] + r * W + c;

            float4 box = pb[n];
            float atn = pd_atan(box);
            float pkx = pk[3*n], pky = pk[3*n+1];
            float overlap = eval_overlap(gc, box, atn, pkx, pky, fs2);
            float score = ps[(size_t)n * NC];
            float alv = score * powf(overlap, 6.0f);
            if (alv < FLT_MIN_NORMAL) alv = 0.f;  // FTZ (matches reference)

            if (alv > 0.f) {
                int slot = atomicAdd(&s_pcnt, 1);
                if (slot < P_CAP) {
                    s_pkey[slot] = ((unsigned long long)__float_as_uint(alv) << 32)
                                 | (unsigned long long)(0xFFFFFFFFu - (unsigned)n);
                    s_pov[slot] = overlap;
                }
                if (n < 512) atomicOr(&s_bm[n >> 5], 1u << (n & 31));
            } else {
                int slot = atomicAdd(&s_bcnt, 1);
                if (slot < B_CAP) { s_bidx[slot] = n; s_bov[slot] = overlap; }
            }
        }
    }
    __syncthreads();

    // ---- warp 0 only: adaptive selection ----
    if (tid >= 32) return;
    int lane = tid;
    int P = min(s_pcnt, P_CAP);
    size_t base = (size_t)b * NA;
    int rounds;

    if (P <= TOPK_) {
        rounds = P;
        if (lane < P) {
            unsigned long long kk = s_pkey[lane];
            int n_w = (int)(0xFFFFFFFFu - (unsigned)(kk & 0xFFFFFFFFull));
            float alv = __uint_as_float((unsigned)(kk >> 32));
            emit_claim(base + n_w, g, alv, s_pov[lane]);
        }
    } else if (P <= 32) {
        rounds = TOPK_;
        unsigned long long key = (lane < P) ? s_pkey[lane] : 0ull;
        int slot = lane;
        #pragma unroll
        for (int kk2 = 2; kk2 <= 32; kk2 <<= 1) {
            #pragma unroll
            for (int j = kk2 >> 1; j > 0; j >>= 1) {
                unsigned long long pkk = __shfl_xor_sync(0xffffffffu, key, j);
                int psl = __shfl_xor_sync(0xffffffffu, slot, j);
                bool lower = (lane & j) == 0;
                bool desc  = (lane & kk2) == 0;
                bool takeMax = (desc == lower);
                bool sw = takeMax ? (pkk > key) : (pkk < key);
                if (sw) { key = pkk; slot = psl; }
            }
        }
        if (lane < TOPK_) {
            int n_w = (int)(0xFFFFFFFFu - (unsigned)(key & 0xFFFFFFFFull));
            float alv = __uint_as_float((unsigned)(key >> 32));
            emit_claim(base + n_w, g, alv, s_pov[slot]);
        }
    } else {
        unsigned long long cur = 0ull; int curs = -1;
        for (int i = lane; i < P; i += 32) {
            unsigned long long kk = s_pkey[i];
            if (kk > cur) { cur = kk; curs = i; }
        }
        rounds = 0;
        #pragma unroll 1
        for (int k = 0; k < TOPK_; k++) {
            unsigned long long bk = cur;
            #pragma unroll
            for (int o = 16; o > 0; o >>= 1) {
                unsigned long long ok = __shfl_xor_sync(0xffffffffu, bk, o);
                if (ok > bk) bk = ok;
            }
            unsigned won = __ballot_sync(0xffffffffu, cur == bk);  // keys unique
            int bl = __ffs(won) - 1;
            if (lane == bl) {
                s_wkey[k] = bk; s_wov[k] = s_pov[curs];
                s_pkey[curs] = 0ull;
                cur = 0ull; curs = -1;
                for (int i = lane; i < P; i += 32) {
                    unsigned long long kk = s_pkey[i];
                    if (kk > cur) { cur = kk; curs = i; }
                }
            }
            rounds++;
        }
        __syncwarp();
        if (lane < rounds) {
            unsigned long long kk = s_wkey[lane];
            int n_w = (int)(0xFFFFFFFFu - (unsigned)(kk & 0xFFFFFFFFull));
            float alv = __uint_as_float((unsigned)(kk >> 32));
            emit_claim(base + n_w, g, alv, s_wov[lane]);
        }
    }

    // zero-pad: remaining winners = lowest-index zero-align anchors (global order)
    int Z = TOPK_ - rounds;
    if (Z > 0) {
        int cutoff = -1;
        if (lane == 0) {
            int cum = 0;
            #pragma unroll 1
            for (int w = 0; w < 16; w++) {
                unsigned z = ~s_bm[w];
                int c = __popc(z);
                if (cum + c >= Z) {
                    int need = Z - cum;
                    while (true) {
                        int bit = __ffs(z) - 1;
                        if (--need == 0) { cutoff = w*32 + bit; break; }
                        z &= z - 1;
                    }
                    break;
                }
                cum += c;
            }
        }
        cutoff = __shfl_sync(0xffffffffu, cutoff, 0);
        int Bc = min(s_bcnt, B_CAP);
        for (int i = lane; i < Bc; i += 32) {
            int n_w = s_bidx[i];
            if (n_w <= cutoff)
                emit_claim(base + n_w, g, 0.f, s_bov[i]);
        }
    }
}

// ---------------- K2: per-anchor resolve + outputs + row maxima (lazy GTC) ----------------
__global__ void __launch_bounds__(256) k2_resolve(
    const float* __restrict__ pd_scores, const float* __restrict__ pd_bboxes,
    const int* __restrict__ gt_labels,  const float* __restrict__ gt_bboxes,
    const float* __restrict__ mask_gt,  const float* __restrict__ gt_kkpts,
    const float* __restrict__ pd_kkpts, const float* __restrict__ sigma,
    const int* __restrict__ regmax_p,
    float* __restrict__ o_tlabels, float* __restrict__ o_tbboxes,
    float* __restrict__ o_fg, float* __restrict__ o_tgi)
{
    __shared__ GTC s_gt[NMAX];
    int b = blockIdx.y;
    int tid = threadIdx.x;
    int n = blockIdx.x * 256 + tid;
    bool active = (n < NA);
    size_t i = (size_t)b * NA + (active ? n : 0);

    unsigned c = 0u;
    if (active) { c = g_cnt[i]; g_cnt[i] = 0u; }   // reset for next graph replay
    float fg = 0.f, al = 0.f, ovown = 0.f;
    int owner = 0;

    if (active && c == 1u) {
        uint4 cl = g_claim[i];
        owner = (int)cl.x;
        al    = __uint_as_float(cl.y);
        ovown = __uint_as_float(cl.z);
        fg = 1.f;
    }

    bool multi = active && (c > 1u);
    if (__syncthreads_or((int)multi)) {
        if (tid < NMAX) make_gtc(s_gt[tid], gt_bboxes, gt_labels, mask_gt, gt_kkpts, b*NMAX + tid);
        __syncthreads();
        if (multi) {
            float rmf = parse_rmf(regmax_p);
            float rmscale = (rmf - 1.f) * 2.f;
            float sg = sigma[0];
            float fs2 = (2.f*sg)*(2.f*sg);
            float ax, ay, aps;
            anchor_decode(n, rmscale, ax, ay, aps);
            float4 box = ((const float4*)pd_bboxes)[i];
            float atn = pd_atan(box);
            float pkx = pd_kkpts[i*3], pky = pd_kkpts[i*3+1];
            float bv = -1.f; int bgi = 0;
            for (int gg = 0; gg < NMAX; gg++) {
                const GTC& gc = s_gt[gg];
                float ov = 0.f;
                if (gc.valid != 0.f) {
                    float din = fminf(fminf(ax - gc.gx1, ay - gc.gy1),
                                      fminf(gc.gx2 - ax, gc.gy2 - ay));
                    if ((din > EPS) && ((aps - gc.gt_size) >= EPS))
                        ov = eval_overlap(gc, box, atn, pkx, pky, fs2);
                }
                if (ov > bv) { bv = ov; bgi = gg; }
            }
            owner = bgi; ovown = bv; fg = 1.f;
            const GTC& go = s_gt[owner];
            float din = fminf(fminf(ax - go.gx1, ay - go.gy1),
                              fminf(go.gx2 - ax, go.gy2 - ay));
            float m = ((go.valid != 0.f) && (din > EPS) && ((aps - go.gt_size) >= EPS)) ? 1.f : 0.f;
            float score = pd_scores[i * NC + go.lbl] * m;
            al = score * powf(ovown, 6.0f);
            if (al < FLT_MIN_NORMAL) al = 0.f;
        }
    }
    if (!active) return;

    int lbl = __ldg(&gt_labels[b * NMAX + owner]); if (lbl < 0) lbl = 0;
    o_tlabels[i] = (float)lbl;
    ((float4*)o_tbboxes)[i] = __ldg(&((const float4*)gt_bboxes)[b * NMAX + owner]);
    o_fg[i]  = fg;
    o_tgi[i] = (float)owner;
    g_anchor_al[i] = al;
    if (fg > 0.f) {
        atomicMax(&g_posalign[b*NMAX + owner], __float_as_uint(al));
        atomicMax(&g_posov   [b*NMAX + owner], __float_as_uint(ovown));
    }
}

// ---------------- K3: sparse scatter of the one-hot scores (rows pre-zeroed in k1) ----------------
__global__ void __launch_bounds__(256) k3_scores(
    const float* __restrict__ o_tlabels, const float* __restrict__ o_fg,
    const float* __restrict__ o_tgi, float* __restrict__ o_tscores)
{
    int i = blockIdx.x * 256 + threadIdx.x;
    if (i >= BS * NA) return;
    int b = i / NA;

    float fg = o_fg[i];
    if (fg > 0.f) {
        int lbl   = (int)o_tlabels[i];
        int owner = (int)o_tgi[i];
        float al = g_anchor_al[i];
        float po = __uint_as_float(g_posov[b*NMAX + owner]);
        float pa = __uint_as_float(g_posalign[b*NMAX + owner]);
        float val = al * po / (pa + EPS);
        o_tscores[(size_t)i * NC + lbl] = val;
    }
}

// ---------------- host ----------------
extern "C" void kernel_launch(void* const* d_in, const int* in_sizes, int n_in,
                              void* d_out, int out_size)
{
    const float* pd_scores = (const float*)d_in[0];
    const float* pd_bboxes = (const float*)d_in[1];
    const int*   gt_labels = (const int*)  d_in[3];
    const float* gt_bboxes = (const float*)d_in[4];
    const float* mask_gt   = (const float*)d_in[5];
    const float* gt_kkpts  = (const float*)d_in[6];
    const float* pd_kkpts  = (const float*)d_in[7];
    const float* sigma     = (const float*)d_in[8];
    const int*   regmax    = (n_in > 10) ? (const int*)d_in[10] : nullptr;

    float* out       = (float*)d_out;
    float* o_tlabels = out;
    float* o_tbboxes = out + (size_t)BS*NA;
    float* o_tscores = out + (size_t)BS*NA*5;
    float* o_fg      = out + (size_t)BS*NA*(5 + NC);
    float* o_tgi     = out + (size_t)BS*NA*(6 + NC);

    k1_metrics<<<BS*NMAX, NT1>>>(pd_scores, pd_bboxes, gt_labels, gt_bboxes,
                                 mask_gt, gt_kkpts, pd_kkpts, sigma, regmax, o_tscores);
    {
        dim3 grid((NA + 255)/256, BS);
        k2_resolve<<<grid, 256>>>(pd_scores, pd_bboxes, gt_labels, gt_bboxes,
                                  mask_gt, gt_kkpts, pd_kkpts, sigma, regmax,
                                  o_tlabels, o_tbboxes, o_fg, o_tgi);
    }
    k3_scores <<<(BS*NA + 255)/256, 256>>>(o_tlabels, o_fg, o_tgi, o_tscores);
}

// round 13
// speedup vs baseline: 1.0884x; 1.0884x over previous
#include <cuda_runtime.h>
#include <math_constants.h>
#include <math.h>

#define BS    16
#define NMAX  64
#define NA    8400
#define NC    80
#define TOPK_ 13
#define EPS   1e-9f
#define CEPS  1e-7f
#define FLT_MIN_NORMAL 1.17549435e-38f
#define P_CAP 320    // in-box candidates <= 15^2+8^2+4^2 = 305
#define B_CAP 320
#define NT1   128

// ---------------- persistent scratch (small) ----------------
__device__ unsigned int g_cnt   [BS*NA];     // zero at load; k2 re-zeroes after read
__device__ uint4        g_claim [BS*NA];     // {g, align_bits, overlap_bits, 0}
__device__ float        g_anchor_al[BS*NA];
__device__ unsigned int g_posalign[BS*NMAX]; // float bits (nonneg)
__device__ unsigned int g_posov   [BS*NMAX];
__device__ float4       g_gtc   [BS*NMAX*4]; // precomputed GTC (4 x float4 per gt)
__device__ float        g_sink;              // DCE guard for prefetch loads

// analytic anchor grid (bitwise-equal to reference's (i+0.5)*s construction)
__device__ __forceinline__ void anchor_decode(int n, float rmscale,
                                              float& ax, float& ay, float& aps) {
    if (n < 6400)      { int r = n / 80;        int c = n - r*80;        ax = (c+0.5f)*8.f;  ay = (r+0.5f)*8.f;  aps = 8.f*rmscale;  }
    else if (n < 8000) { int r = (n-6400) / 40; int c = (n-6400) - r*40; ax = (c+0.5f)*16.f; ay = (r+0.5f)*16.f; aps = 16.f*rmscale; }
    else               { int r = (n-8000) / 20; int c = (n-8000) - r*20; ax = (c+0.5f)*32.f; ay = (r+0.5f)*32.f; aps = 32.f*rmscale; }
}

struct GTC {
    float gx1, gy1, gx2, gy2;
    float w1h1, atan1, gsx, gsy;
    float gt_size, areap, kx, ky;
    float kmask, kden, valid;
    int   lbl;
};

__device__ __forceinline__ void make_gtc(GTC& g, const float* gt_bboxes,
                                         const int* gt_labels, const float* mask_gt,
                                         const float* gt_kkpts, int bg) {
    float gx1 = gt_bboxes[bg*4+0], gy1 = gt_bboxes[bg*4+1];
    float gx2 = gt_bboxes[bg*4+2], gy2 = gt_bboxes[bg*4+3];
    g.gx1 = gx1; g.gy1 = gy1; g.gx2 = gx2; g.gy2 = gy2;
    float w1 = gx2 - gx1, h1 = gy2 - gy1 + CEPS;
    g.atan1 = atanf(w1 / h1);
    g.w1h1  = w1 * h1;
    g.gsx = gx1 + gx2; g.gsy = gy1 + gy2;
    float gw = gx2 - gx1, gh = gy2 - gy1;
    g.gt_size = 0.5f * (gw + gh);
    g.areap   = gw * gh * 0.53f + 1e-7f;
    g.kx = gt_kkpts[bg*3+0]; g.ky = gt_kkpts[bg*3+1];
    float kv = gt_kkpts[bg*3+2];
    g.kmask = (kv != 0.f) ? 1.f : 0.f;
    g.kden  = g.kmask + 1e-7f;
    g.valid = mask_gt[bg];
    g.lbl   = gt_labels[bg];
}

__device__ __forceinline__ void load_gtc(GTC& g, int bg) {
    const float4* p = &g_gtc[bg*4];
    float4 a = p[0], b4 = p[1], c = p[2], d = p[3];
    g.gx1 = a.x; g.gy1 = a.y; g.gx2 = a.z; g.gy2 = a.w;
    g.w1h1 = b4.x; g.atan1 = b4.y; g.gsx = b4.z; g.gsy = b4.w;
    g.gt_size = c.x; g.areap = c.y; g.kx = c.z; g.ky = c.w;
    g.kmask = d.x; g.kden = d.y; g.valid = d.z; g.lbl = __float_as_int(d.w);
}

// overlap for an m==1 cell; same arithmetic sequence as all passing rounds
__device__ __forceinline__ float eval_overlap(const GTC& g, float4 box, float atn,
                                              float pkx, float pky, float fs2) {
    const float inv_pi2_4 = 0.4052847345693511f;
    float px1 = box.x, py1 = box.y, px2 = box.z, py2 = box.w;
    float w2 = px2 - px1, h2 = py2 - py1 + CEPS;
    float iw = fminf(g.gx2, px2) - fmaxf(g.gx1, px1);
    float ih = fminf(g.gy2, py2) - fmaxf(g.gy1, py1);
    float inter = fmaxf(iw, 0.f) * fmaxf(ih, 0.f);
    float uni = g.w1h1 + w2 * h2 - inter + CEPS;
    float iou = inter / uni;
    float cw = fmaxf(g.gx2, px2) - fminf(g.gx1, px1);
    float ch = fmaxf(g.gy2, py2) - fminf(g.gy1, py1);
    float c2 = cw*cw + ch*ch + CEPS;
    float dx = px1 + px2 - g.gsx, dy = py1 + py2 - g.gsy;
    float rho2 = (dx*dx + dy*dy) / 4.0f;
    float dat = atn - g.atan1;
    float v = inv_pi2_4 * (dat * dat);
    float a = v / (v - iou + (1.f + CEPS));
    float cio = iou - (rho2 / c2 + v * a);
    cio = fmaxf(cio, 0.f);
    float ddx = pkx - g.kx, ddy = pky - g.ky;
    float d2 = ddx*ddx + ddy*ddy;
    float e = d2 / fs2 / g.areap / 2.0f;
    float kio = (expf(-e) * g.kmask) / g.kden;
    float overlap = (cio + kio) / 2.0f;
    if (overlap < FLT_MIN_NORMAL) overlap = 0.f;   // FTZ (matches reference)
    return overlap;
}

__device__ __forceinline__ float parse_rmf(const int* regmax_p) {
    float rmf = 16.f;
    if (regmax_p) {
        int v = regmax_p[0];
        if (v >= 1 && v <= 65536) rmf = (float)v;
        else { float fv = __int_as_float(v); if (fv >= 1.f && fv <= 65536.f) rmf = fv; }
    }
    return rmf;
}

__device__ __forceinline__ float pd_atan(float4 box) {
    float w2 = box.z - box.x;
    float h2 = box.w - box.y + CEPS;
    return atanf(w2 / h2);
}

// race-safe claim: plain STG.128 + RED.ADD; data only trusted when final cnt==1
__device__ __forceinline__ void emit_claim(size_t idx, int g, float alv, float ov) {
    g_claim[idx] = make_uint4((unsigned)g, __float_as_uint(alv), __float_as_uint(ov), 0u);
    atomicAdd(&g_cnt[idx], 1u);
}

// ---------------- K0: warp-per-gt GTC precompute + scatter prefetch into L2 ----------------
__global__ void __launch_bounds__(128) k0_prefetch(
    const float* __restrict__ pd_scores, const float* __restrict__ pd_bboxes,
    const int* __restrict__ gt_labels,  const float* __restrict__ gt_bboxes,
    const float* __restrict__ mask_gt,  const float* __restrict__ gt_kkpts,
    const float* __restrict__ pd_kkpts, const int* __restrict__ regmax_p)
{
    int w = (blockIdx.x * 128 + threadIdx.x) >> 5;
    int lane = threadIdx.x & 31;
    if (w >= BS * NMAX) return;
    int bg = w;
    int b  = bg >> 6;

    if (lane == 0) {
        GTC gc; make_gtc(gc, gt_bboxes, gt_labels, mask_gt, gt_kkpts, bg);
        float4* p = &g_gtc[bg*4];
        p[0] = make_float4(gc.gx1, gc.gy1, gc.gx2, gc.gy2);
        p[1] = make_float4(gc.w1h1, gc.atan1, gc.gsx, gc.gsy);
        p[2] = make_float4(gc.gt_size, gc.areap, gc.kx, gc.ky);
        p[3] = make_float4(gc.kmask, gc.kden, gc.valid, __int_as_float(gc.lbl));
    }
    if (mask_gt[bg] == 0.f) return;

    // rect bounds (superset of k1's candidates) — touch every cell's score/box/kpt sectors
    float gx1 = gt_bboxes[bg*4+0], gy1 = gt_bboxes[bg*4+1];
    float gx2 = gt_bboxes[bg*4+2], gy2 = gt_bboxes[bg*4+3];
    int   lbl = gt_labels[bg];
    float rmf = parse_rmf(regmax_p);
    float rmscale = (rmf - 1.f) * 2.f;
    float gt_size = 0.5f * ((gx2 - gx1) + (gy2 - gy1));

    const float* ps = pd_scores + (size_t)b * NA * NC + lbl;
    const float* pbx = pd_bboxes + (size_t)b * NA * 4;
    const float* pk  = pd_kkpts  + (size_t)b * NA * 3;

    const int   L_base[3] = {0, 6400, 8000};
    const int   L_W[3]    = {80, 40, 20};
    const float L_s[3]    = {8.f, 16.f, 32.f};

    float acc = 0.f;
    #pragma unroll
    for (int l = 0; l < 3; l++) {
        float s = L_s[l];
        if (!((s * rmscale - gt_size) >= EPS)) continue;
        int W = L_W[l];
        float inv_s = 1.f / s;
        int c_lo = max(0,     (int)floorf(gx1 * inv_s - 0.5f) - 1);
        int c_hi = min(W - 1, (int)floorf(gx2 * inv_s - 0.5f) + 1);
        int r_lo = max(0,     (int)floorf(gy1 * inv_s - 0.5f) - 1);
        int r_hi = min(W - 1, (int)floorf(gy2 * inv_s - 0.5f) + 1);
        int ncc = c_hi - c_lo + 1, nrr = r_hi - r_lo + 1;
        if (ncc <= 0 || nrr <= 0) continue;
        int tot = ncc * nrr;
        for (int j = lane; j < tot; j += 32) {
            int r = r_lo + j / ncc, c = c_lo + j % ncc;
            int n = L_base[l] + r * W + c;
            acc += __ldg(&ps[(size_t)n * NC]);     // score sector
            acc += __ldg(&pbx[(size_t)n * 4]);     // box sector (16B within one 32B sector)
            acc += __ldg(&pk[(size_t)n * 3]);      // kpt sectors (12B may straddle)
            acc += __ldg(&pk[(size_t)n * 3 + 2]);
        }
    }
    if (acc == 1.2345678e38f) g_sink = acc;   // unprovable-false: keeps the loads
}

// ---------------- K1: block-per-gt build + adaptive top-13 (gathers hit warm L2) ----------------
__global__ void __launch_bounds__(NT1) k1_metrics(
    const float* __restrict__ pd_scores, const float* __restrict__ pd_bboxes,
    const float* __restrict__ pd_kkpts, const float* __restrict__ sigma,
    const int* __restrict__ regmax_p)
{
    __shared__ unsigned long long s_pkey[P_CAP];
    __shared__ float s_pov[P_CAP];
    __shared__ int   s_bidx[B_CAP];
    __shared__ float s_bov[B_CAP];
    __shared__ unsigned int s_bm[16];   // 512-bit bitmap (cutoff < 512 provably)
    __shared__ int s_pcnt, s_bcnt;
    __shared__ unsigned long long s_wkey[TOPK_];
    __shared__ float s_wov[TOPK_];

    int bg = blockIdx.x;
    int b  = bg >> 6;
    int g  = bg & 63;
    int tid = threadIdx.x;

    if (tid == 0) { g_posalign[bg] = 0u; g_posov[bg] = 0u; s_pcnt = 0; s_bcnt = 0; }
    if (tid < 16) s_bm[tid] = 0u;

    GTC gc; load_gtc(gc, bg);
    __syncthreads();
    if (gc.valid == 0.f) return;

    float rmf = parse_rmf(regmax_p);
    float rmscale = (rmf - 1.f) * 2.f;
    float sg = sigma[0];
    float fs2 = (2.f*sg)*(2.f*sg);

    const float4* pb = (const float4*)(pd_bboxes + (size_t)b * NA * 4);
    const float*  ps = pd_scores + (size_t)b * NA * NC + gc.lbl;
    const float*  pk = pd_kkpts  + (size_t)b * NA * 3;

    const int   L_base[3] = {0, 6400, 8000};
    const int   L_W[3]    = {80, 40, 20};
    const float L_s[3]    = {8.f, 16.f, 32.f};

    #pragma unroll
    for (int l = 0; l < 3; l++) {
        float s = L_s[l];
        float aps = s * rmscale;
        if (!((aps - gc.gt_size) >= EPS)) continue;
        int W = L_W[l];
        float inv_s = 1.f / s;
        int c_lo = max(0,     (int)floorf(gc.gx1 * inv_s - 0.5f) - 1);
        int c_hi = min(W - 1, (int)floorf(gc.gx2 * inv_s - 0.5f) + 1);
        int r_lo = max(0,     (int)floorf(gc.gy1 * inv_s - 0.5f) - 1);
        int r_hi = min(W - 1, (int)floorf(gc.gy2 * inv_s - 0.5f) + 1);
        int ncc = c_hi - c_lo + 1, nrr = r_hi - r_lo + 1;
        if (ncc <= 0 || nrr <= 0) continue;
        int tot = ncc * nrr;
        for (int j = tid; j < tot; j += NT1) {
            int r = r_lo + j / ncc, c = c_lo + j % ncc;
            float ax = (c + 0.5f) * s, ay = (r + 0.5f) * s;
            float din = fminf(fminf(ax - gc.gx1, ay - gc.gy1),
                              fminf(gc.gx2 - ax, gc.gy2 - ay));
            if (!(din > EPS)) continue;          // exact in-box test
            int n = L_base[l] + r * W + c;

            float4 box = pb[n];
            float atn = pd_atan(box);
            float pkx = pk[3*n], pky = pk[3*n+1];
            float overlap = eval_overlap(gc, box, atn, pkx, pky, fs2);
            float score = ps[(size_t)n * NC];
            float alv = score * powf(overlap, 6.0f);
            if (alv < FLT_MIN_NORMAL) alv = 0.f;  // FTZ (matches reference)

            if (alv > 0.f) {
                int slot = atomicAdd(&s_pcnt, 1);
                if (slot < P_CAP) {
                    s_pkey[slot] = ((unsigned long long)__float_as_uint(alv) << 32)
                                 | (unsigned long long)(0xFFFFFFFFu - (unsigned)n);
                    s_pov[slot] = overlap;
                }
                if (n < 512) atomicOr(&s_bm[n >> 5], 1u << (n & 31));
            } else {
                int slot = atomicAdd(&s_bcnt, 1);
                if (slot < B_CAP) { s_bidx[slot] = n; s_bov[slot] = overlap; }
            }
        }
    }
    __syncthreads();

    // ---- warp 0 only: adaptive selection ----
    if (tid >= 32) return;
    int lane = tid;
    int P = min(s_pcnt, P_CAP);
    size_t base = (size_t)b * NA;
    int rounds;

    if (P <= TOPK_) {
        rounds = P;
        if (lane < P) {
            unsigned long long kk = s_pkey[lane];
            int n_w = (int)(0xFFFFFFFFu - (unsigned)(kk & 0xFFFFFFFFull));
            float alv = __uint_as_float((unsigned)(kk >> 32));
            emit_claim(base + n_w, g, alv, s_pov[lane]);
        }
    } else if (P <= 32) {
        rounds = TOPK_;
        unsigned long long key = (lane < P) ? s_pkey[lane] : 0ull;
        int slot = lane;
        #pragma unroll
        for (int kk2 = 2; kk2 <= 32; kk2 <<= 1) {
            #pragma unroll
            for (int j = kk2 >> 1; j > 0; j >>= 1) {
                unsigned long long pkk = __shfl_xor_sync(0xffffffffu, key, j);
                int psl = __shfl_xor_sync(0xffffffffu, slot, j);
                bool lower = (lane & j) == 0;
                bool desc  = (lane & kk2) == 0;
                bool takeMax = (desc == lower);
                bool sw = takeMax ? (pkk > key) : (pkk < key);
                if (sw) { key = pkk; slot = psl; }
            }
        }
        if (lane < TOPK_) {
            int n_w = (int)(0xFFFFFFFFu - (unsigned)(key & 0xFFFFFFFFull));
            float alv = __uint_as_float((unsigned)(key >> 32));
            emit_claim(base + n_w, g, alv, s_pov[slot]);
        }
    } else {
        unsigned long long cur = 0ull; int curs = -1;
        for (int i = lane; i < P; i += 32) {
            unsigned long long kk = s_pkey[i];
            if (kk > cur) { cur = kk; curs = i; }
        }
        rounds = 0;
        #pragma unroll 1
        for (int k = 0; k < TOPK_; k++) {
            unsigned long long bk = cur;
            #pragma unroll
            for (int o = 16; o > 0; o >>= 1) {
                unsigned long long ok = __shfl_xor_sync(0xffffffffu, bk, o);
                if (ok > bk) bk = ok;
            }
            unsigned won = __ballot_sync(0xffffffffu, cur == bk);  // keys unique
            int bl = __ffs(won) - 1;
            if (lane == bl) {
                s_wkey[k] = bk; s_wov[k] = s_pov[curs];
                s_pkey[curs] = 0ull;
                cur = 0ull; curs = -1;
                for (int i = lane; i < P; i += 32) {
                    unsigned long long kk = s_pkey[i];
                    if (kk > cur) { cur = kk; curs = i; }
                }
            }
            rounds++;
        }
        __syncwarp();
        if (lane < rounds) {
            unsigned long long kk = s_wkey[lane];
            int n_w = (int)(0xFFFFFFFFu - (unsigned)(kk & 0xFFFFFFFFull));
            float alv = __uint_as_float((unsigned)(kk >> 32));
            emit_claim(base + n_w, g, alv, s_wov[lane]);
        }
    }

    // zero-pad: remaining winners = lowest-index zero-align anchors (global order)
    int Z = TOPK_ - rounds;
    if (Z > 0) {
        int cutoff = -1;
        if (lane == 0) {
            int cum = 0;
            #pragma unroll 1
            for (int w = 0; w < 16; w++) {
                unsigned z = ~s_bm[w];
                int c = __popc(z);
                if (cum + c >= Z) {
                    int need = Z - cum;
                    while (true) {
                        int bit = __ffs(z) - 1;
                        if (--need == 0) { cutoff = w*32 + bit; break; }
                        z &= z - 1;
                    }
                    break;
                }
                cum += c;
            }
        }
        cutoff = __shfl_sync(0xffffffffu, cutoff, 0);
        int Bc = min(s_bcnt, B_CAP);
        for (int i = lane; i < Bc; i += 32) {
            int n_w = s_bidx[i];
            if (n_w <= cutoff)
                emit_claim(base + n_w, g, 0.f, s_bov[i]);
        }
    }
}

// ---------------- K2: per-anchor resolve + outputs + row maxima (lazy GTC from table) ----------------
__global__ void __launch_bounds__(256) k2_resolve(
    const float* __restrict__ pd_scores, const float* __restrict__ pd_bboxes,
    const int* __restrict__ gt_labels,  const float* __restrict__ gt_bboxes,
    const float* __restrict__ pd_kkpts, const float* __restrict__ sigma,
    const int* __restrict__ regmax_p,
    float* __restrict__ o_tlabels, float* __restrict__ o_tbboxes,
    float* __restrict__ o_fg, float* __restrict__ o_tgi)
{
    __shared__ GTC s_gt[NMAX];
    int b = blockIdx.y;
    int tid = threadIdx.x;
    int n = blockIdx.x * 256 + tid;
    bool active = (n < NA);
    size_t i = (size_t)b * NA + (active ? n : 0);

    unsigned c = 0u;
    if (active) { c = g_cnt[i]; g_cnt[i] = 0u; }   // reset for next graph replay
    float fg = 0.f, al = 0.f, ovown = 0.f;
    int owner = 0;

    if (active && c == 1u) {
        uint4 cl = g_claim[i];
        owner = (int)cl.x;
        al    = __uint_as_float(cl.y);
        ovown = __uint_as_float(cl.z);
        fg = 1.f;
    }

    bool multi = active && (c > 1u);
    if (__syncthreads_or((int)multi)) {
        if (tid < NMAX) load_gtc(s_gt[tid], b*NMAX + tid);
        __syncthreads();
        if (multi) {
            float rmf = parse_rmf(regmax_p);
            float rmscale = (rmf - 1.f) * 2.f;
            float sg = sigma[0];
            float fs2 = (2.f*sg)*(2.f*sg);
            float ax, ay, aps;
            anchor_decode(n, rmscale, ax, ay, aps);
            float4 box = ((const float4*)pd_bboxes)[i];
            float atn = pd_atan(box);
            float pkx = pd_kkpts[i*3], pky = pd_kkpts[i*3+1];
            float bv = -1.f; int bgi = 0;
            for (int gg = 0; gg < NMAX; gg++) {
                const GTC& gc = s_gt[gg];
                float ov = 0.f;
                if (gc.valid != 0.f) {
                    float din = fminf(fminf(ax - gc.gx1, ay - gc.gy1),
                                      fminf(gc.gx2 - ax, gc.gy2 - ay));
                    if ((din > EPS) && ((aps - gc.gt_size) >= EPS))
                        ov = eval_overlap(gc, box, atn, pkx, pky, fs2);
                }
                if (ov > bv) { bv = ov; bgi = gg; }
            }
            owner = bgi; ovown = bv; fg = 1.f;
            const GTC& go = s_gt[owner];
            float din = fminf(fminf(ax - go.gx1, ay - go.gy1),
                              fminf(go.gx2 - ax, go.gy2 - ay));
            float m = ((go.valid != 0.f) && (din > EPS) && ((aps - go.gt_size) >= EPS)) ? 1.f : 0.f;
            float score = pd_scores[i * NC + go.lbl] * m;
            al = score * powf(ovown, 6.0f);
            if (al < FLT_MIN_NORMAL) al = 0.f;
        }
    }
    if (!active) return;

    int lbl = __ldg(&gt_labels[b * NMAX + owner]); if (lbl < 0) lbl = 0;
    o_tlabels[i] = (float)lbl;
    ((float4*)o_tbboxes)[i] = __ldg(&((const float4*)gt_bboxes)[b * NMAX + owner]);
    o_fg[i]  = fg;
    o_tgi[i] = (float)owner;
    g_anchor_al[i] = al;
    if (fg > 0.f) {
        atomicMax(&g_posalign[b*NMAX + owner], __float_as_uint(al));
        atomicMax(&g_posov   [b*NMAX + owner], __float_as_uint(ovown));
    }
}

// ---------------- K3: norm + tscores (warp per anchor, STG.128) ----------------
__global__ void __launch_bounds__(256) k3_scores(
    const float* __restrict__ o_tlabels, const float* __restrict__ o_fg,
    const float* __restrict__ o_tgi, float* __restrict__ o_tscores)
{
    int w = blockIdx.x * 8 + (threadIdx.x >> 5);
    if (w >= BS * NA) return;
    int lane = threadIdx.x & 31;
    int b = w / NA;

    float fg = o_fg[w];
    int lbl = (int)o_tlabels[w];
    float val = 0.f;
    if (fg > 0.f) {
        int owner = (int)o_tgi[w];
        float al = g_anchor_al[w];
        float po = __uint_as_float(g_posov[b*NMAX + owner]);
        float pa = __uint_as_float(g_posalign[b*NMAX + owner]);
        val = al * po / (pa + EPS);
    }
    if (lane < 20) {
        int base = lane * 4;
        float4 v;
        v.x = (lbl == base + 0) ? val : 0.f;
        v.y = (lbl == base + 1) ? val : 0.f;
        v.z = (lbl == base + 2) ? val : 0.f;
        v.w = (lbl == base + 3) ? val : 0.f;
        ((float4*)(o_tscores + (size_t)w * NC))[lane] = v;
    }
}

// ---------------- host ----------------
extern "C" void kernel_launch(void* const* d_in, const int* in_sizes, int n_in,
                              void* d_out, int out_size)
{
    const float* pd_scores = (const float*)d_in[0];
    const float* pd_bboxes = (const float*)d_in[1];
    const int*   gt_labels = (const int*)  d_in[3];
    const float* gt_bboxes = (const float*)d_in[4];
    const float* mask_gt   = (const float*)d_in[5];
    const float* gt_kkpts  = (const float*)d_in[6];
    const float* pd_kkpts  = (const float*)d_in[7];
    const float* sigma     = (const float*)d_in[8];
    const int*   regmax    = (n_in > 10) ? (const int*)d_in[10] : nullptr;

    float* out       = (float*)d_out;
    float* o_tlabels = out;
    float* o_tbboxes = out + (size_t)BS*NA;
    float* o_tscores = out + (size_t)BS*NA*5;
    float* o_fg      = out + (size_t)BS*NA*(5 + NC);
    float* o_tgi     = out + (size_t)BS*NA*(6 + NC);

    k0_prefetch<<<(BS*NMAX*32 + 127)/128, 128>>>(pd_scores, pd_bboxes, gt_labels,
                                                 gt_bboxes, mask_gt, gt_kkpts,
                                                 pd_kkpts, regmax);
    k1_metrics<<<BS*NMAX, NT1>>>(pd_scores, pd_bboxes, pd_kkpts, sigma, regmax);
    {
        dim3 grid((NA + 255)/256, BS);
        k2_resolve<<<grid, 256>>>(pd_scores, pd_bboxes, gt_labels, gt_bboxes,
                                  pd_kkpts, sigma, regmax,
                                  o_tlabels, o_tbboxes, o_fg, o_tgi);
    }
    k3_scores <<<(BS*NA + 7)/8, 256>>>(o_tlabels, o_fg, o_tgi, o_tscores);
}

// round 14
// speedup vs baseline: 1.4345x; 1.3180x over previous
#include <cuda_runtime.h>
#include <math_constants.h>
#include <math.h>

#define BS    16
#define NMAX  64
#define NA    8400
#define NC    80
#define TOPK_ 13
#define EPS   1e-9f
#define CEPS  1e-7f
#define FLT_MIN_NORMAL 1.17549435e-38f
#define P_CAP 320    // in-box candidates <= 15^2+8^2+4^2 = 305
#define B_CAP 320
#define NT1   128

// ---------------- persistent scratch (small) ----------------
__device__ unsigned int g_cnt   [BS*NA];     // zero at load; k2 re-zeroes after read
__device__ uint4        g_claim [BS*NA];     // {g, align_bits, overlap_bits, 0}
__device__ float        g_anchor_al[BS*NA];
__device__ unsigned int g_posalign[BS*NMAX]; // float bits (nonneg)
__device__ unsigned int g_posov   [BS*NMAX];

// analytic anchor grid (bitwise-equal to reference's (i+0.5)*s construction)
__device__ __forceinline__ void anchor_decode(int n, float rmscale,
                                              float& ax, float& ay, float& aps) {
    if (n < 6400)      { int r = n / 80;        int c = n - r*80;        ax = (c+0.5f)*8.f;  ay = (r+0.5f)*8.f;  aps = 8.f*rmscale;  }
    else if (n < 8000) { int r = (n-6400) / 40; int c = (n-6400) - r*40; ax = (c+0.5f)*16.f; ay = (r+0.5f)*16.f; aps = 16.f*rmscale; }
    else               { int r = (n-8000) / 20; int c = (n-8000) - r*20; ax = (c+0.5f)*32.f; ay = (r+0.5f)*32.f; aps = 32.f*rmscale; }
}

struct GTC {
    float gx1, gy1, gx2, gy2;
    float w1h1, atan1, gsx, gsy;
    float gt_size, areap, kx, ky;
    float kmask, kden, valid;
    int   lbl;
};

__device__ __forceinline__ void make_gtc(GTC& g, const float* gt_bboxes,
                                         const int* gt_labels, const float* mask_gt,
                                         const float* gt_kkpts, int bg) {
    float gx1 = gt_bboxes[bg*4+0], gy1 = gt_bboxes[bg*4+1];
    float gx2 = gt_bboxes[bg*4+2], gy2 = gt_bboxes[bg*4+3];
    g.gx1 = gx1; g.gy1 = gy1; g.gx2 = gx2; g.gy2 = gy2;
    float w1 = gx2 - gx1, h1 = gy2 - gy1 + CEPS;
    g.atan1 = atanf(w1 / h1);
    g.w1h1  = w1 * h1;
    g.gsx = gx1 + gx2; g.gsy = gy1 + gy2;
    float gw = gx2 - gx1, gh = gy2 - gy1;
    g.gt_size = 0.5f * (gw + gh);
    g.areap   = gw * gh * 0.53f + 1e-7f;
    g.kx = gt_kkpts[bg*3+0]; g.ky = gt_kkpts[bg*3+1];
    float kv = gt_kkpts[bg*3+2];
    g.kmask = (kv != 0.f) ? 1.f : 0.f;
    g.kden  = g.kmask + 1e-7f;
    g.valid = mask_gt[bg];
    g.lbl   = gt_labels[bg];
}

// overlap for an m==1 cell; same arithmetic sequence as all passing rounds
__device__ __forceinline__ float eval_overlap(const GTC& g, float4 box, float atn,
                                              float pkx, float pky, float fs2) {
    const float inv_pi2_4 = 0.4052847345693511f;
    float px1 = box.x, py1 = box.y, px2 = box.z, py2 = box.w;
    float w2 = px2 - px1, h2 = py2 - py1 + CEPS;
    float iw = fminf(g.gx2, px2) - fmaxf(g.gx1, px1);
    float ih = fminf(g.gy2, py2) - fmaxf(g.gy1, py1);
    float inter = fmaxf(iw, 0.f) * fmaxf(ih, 0.f);
    float uni = g.w1h1 + w2 * h2 - inter + CEPS;
    float iou = inter / uni;
    float cw = fmaxf(g.gx2, px2) - fminf(g.gx1, px1);
    float ch = fmaxf(g.gy2, py2) - fminf(g.gy1, py1);
    float c2 = cw*cw + ch*ch + CEPS;
    float dx = px1 + px2 - g.gsx, dy = py1 + py2 - g.gsy;
    float rho2 = (dx*dx + dy*dy) / 4.0f;
    float dat = atn - g.atan1;
    float v = inv_pi2_4 * (dat * dat);
    float a = v / (v - iou + (1.f + CEPS));
    float cio = iou - (rho2 / c2 + v * a);
    cio = fmaxf(cio, 0.f);
    float ddx = pkx - g.kx, ddy = pky - g.ky;
    float d2 = ddx*ddx + ddy*ddy;
    float e = d2 / fs2 / g.areap / 2.0f;
    float kio = (expf(-e) * g.kmask) / g.kden;
    float overlap = (cio + kio) / 2.0f;
    if (overlap < FLT_MIN_NORMAL) overlap = 0.f;   // FTZ (matches reference)
    return overlap;
}

__device__ __forceinline__ float parse_rmf(const int* regmax_p) {
    float rmf = 16.f;
    if (regmax_p) {
        int v = regmax_p[0];
        if (v >= 1 && v <= 65536) rmf = (float)v;
        else { float fv = __int_as_float(v); if (fv >= 1.f && fv <= 65536.f) rmf = fv; }
    }
    return rmf;
}

__device__ __forceinline__ float pd_atan(float4 box) {
    float w2 = box.z - box.x;
    float h2 = box.w - box.y + CEPS;
    return atanf(w2 / h2);
}

// race-safe claim: plain STG.128 + RED.ADD; data only trusted when final cnt==1
__device__ __forceinline__ void emit_claim(size_t idx, int g, float alv, float ov) {
    g_claim[idx] = make_uint4((unsigned)g, __float_as_uint(alv), __float_as_uint(ov), 0u);
    atomicAdd(&g_cnt[idx], 1u);
}

// ---------------- K1: block-per-gt build + adaptive top-13 (R10 state) ----------------
__global__ void __launch_bounds__(NT1) k1_metrics(
    const float* __restrict__ pd_scores, const float* __restrict__ pd_bboxes,
    const int* __restrict__ gt_labels,  const float* __restrict__ gt_bboxes,
    const float* __restrict__ mask_gt,  const float* __restrict__ gt_kkpts,
    const float* __restrict__ pd_kkpts, const float* __restrict__ sigma,
    const int* __restrict__ regmax_p)
{
    __shared__ unsigned long long s_pkey[P_CAP];
    __shared__ float s_pov[P_CAP];
    __shared__ int   s_bidx[B_CAP];
    __shared__ float s_bov[B_CAP];
    __shared__ unsigned int s_bm[16];   // 512-bit bitmap (cutoff < 512 provably)
    __shared__ int s_pcnt, s_bcnt;
    __shared__ unsigned long long s_wkey[TOPK_];
    __shared__ float s_wov[TOPK_];

    int bg = blockIdx.x;
    int b  = bg >> 6;
    int g  = bg & 63;
    int tid = threadIdx.x;

    if (tid == 0) { g_posalign[bg] = 0u; g_posov[bg] = 0u; s_pcnt = 0; s_bcnt = 0; }
    if (tid < 16) s_bm[tid] = 0u;

    float mgt = mask_gt[bg];
    __syncthreads();
    if (mgt == 0.f) return;

    float rmf = parse_rmf(regmax_p);
    float rmscale = (rmf - 1.f) * 2.f;
    float sg = sigma[0];
    float fs2 = (2.f*sg)*(2.f*sg);

    GTC gc; make_gtc(gc, gt_bboxes, gt_labels, mask_gt, gt_kkpts, bg);

    const float4* pb = (const float4*)(pd_bboxes + (size_t)b * NA * 4);
    const float*  ps = pd_scores + (size_t)b * NA * NC + gc.lbl;
    const float*  pk = pd_kkpts  + (size_t)b * NA * 3;

    const int   L_base[3] = {0, 6400, 8000};
    const int   L_W[3]    = {80, 40, 20};
    const float L_s[3]    = {8.f, 16.f, 32.f};

    #pragma unroll
    for (int l = 0; l < 3; l++) {
        float s = L_s[l];
        float aps = s * rmscale;
        if (!((aps - gc.gt_size) >= EPS)) continue;
        int W = L_W[l];
        float inv_s = 1.f / s;
        int c_lo = max(0,     (int)floorf(gc.gx1 * inv_s - 0.5f) - 1);
        int c_hi = min(W - 1, (int)floorf(gc.gx2 * inv_s - 0.5f) + 1);
        int r_lo = max(0,     (int)floorf(gc.gy1 * inv_s - 0.5f) - 1);
        int r_hi = min(W - 1, (int)floorf(gc.gy2 * inv_s - 0.5f) + 1);
        int ncc = c_hi - c_lo + 1, nrr = r_hi - r_lo + 1;
        if (ncc <= 0 || nrr <= 0) continue;
        int tot = ncc * nrr;
        for (int j = tid; j < tot; j += NT1) {
            int r = r_lo + j / ncc, c = c_lo + j % ncc;
            float ax = (c + 0.5f) * s, ay = (r + 0.5f) * s;
            float din = fminf(fminf(ax - gc.gx1, ay - gc.gy1),
                              fminf(gc.gx2 - ax, gc.gy2 - ay));
            if (!(din > EPS)) continue;          // exact in-box test
            int n = L_base[l] + r * W + c;

            float4 box = pb[n];
            float atn = pd_atan(box);
            float pkx = pk[3*n], pky = pk[3*n+1];
            float overlap = eval_overlap(gc, box, atn, pkx, pky, fs2);
            float score = ps[(size_t)n * NC];
            float alv = score * powf(overlap, 6.0f);
            if (alv < FLT_MIN_NORMAL) alv = 0.f;  // FTZ (matches reference)

            if (alv > 0.f) {
                int slot = atomicAdd(&s_pcnt, 1);
                if (slot < P_CAP) {
                    s_pkey[slot] = ((unsigned long long)__float_as_uint(alv) << 32)
                                 | (unsigned long long)(0xFFFFFFFFu - (unsigned)n);
                    s_pov[slot] = overlap;
                }
                if (n < 512) atomicOr(&s_bm[n >> 5], 1u << (n & 31));
            } else {
                int slot = atomicAdd(&s_bcnt, 1);
                if (slot < B_CAP) { s_bidx[slot] = n; s_bov[slot] = overlap; }
            }
        }
    }
    __syncthreads();

    // ---- warp 0 only: adaptive selection ----
    if (tid >= 32) return;
    int lane = tid;
    int P = min(s_pcnt, P_CAP);
    size_t base = (size_t)b * NA;
    int rounds;

    if (P <= TOPK_) {
        rounds = P;
        if (lane < P) {
            unsigned long long kk = s_pkey[lane];
            int n_w = (int)(0xFFFFFFFFu - (unsigned)(kk & 0xFFFFFFFFull));
            float alv = __uint_as_float((unsigned)(kk >> 32));
            emit_claim(base + n_w, g, alv, s_pov[lane]);
        }
    } else if (P <= 32) {
        rounds = TOPK_;
        unsigned long long key = (lane < P) ? s_pkey[lane] : 0ull;
        int slot = lane;
        #pragma unroll
        for (int kk2 = 2; kk2 <= 32; kk2 <<= 1) {
            #pragma unroll
            for (int j = kk2 >> 1; j > 0; j >>= 1) {
                unsigned long long pkk = __shfl_xor_sync(0xffffffffu, key, j);
                int psl = __shfl_xor_sync(0xffffffffu, slot, j);
                bool lower = (lane & j) == 0;
                bool desc  = (lane & kk2) == 0;
                bool takeMax = (desc == lower);
                bool sw = takeMax ? (pkk > key) : (pkk < key);
                if (sw) { key = pkk; slot = psl; }
            }
        }
        if (lane < TOPK_) {
            int n_w = (int)(0xFFFFFFFFu - (unsigned)(key & 0xFFFFFFFFull));
            float alv = __uint_as_float((unsigned)(key >> 32));
            emit_claim(base + n_w, g, alv, s_pov[slot]);
        }
    } else {
        unsigned long long cur = 0ull; int curs = -1;
        for (int i = lane; i < P; i += 32) {
            unsigned long long kk = s_pkey[i];
            if (kk > cur) { cur = kk; curs = i; }
        }
        rounds = 0;
        #pragma unroll 1
        for (int k = 0; k < TOPK_; k++) {
            unsigned long long bk = cur;
            #pragma unroll
            for (int o = 16; o > 0; o >>= 1) {
                unsigned long long ok = __shfl_xor_sync(0xffffffffu, bk, o);
                if (ok > bk) bk = ok;
            }
            unsigned won = __ballot_sync(0xffffffffu, cur == bk);  // keys unique
            int bl = __ffs(won) - 1;
            if (lane == bl) {
                s_wkey[k] = bk; s_wov[k] = s_pov[curs];
                s_pkey[curs] = 0ull;
                cur = 0ull; curs = -1;
                for (int i = lane; i < P; i += 32) {
                    unsigned long long kk = s_pkey[i];
                    if (kk > cur) { cur = kk; curs = i; }
                }
            }
            rounds++;
        }
        __syncwarp();
        if (lane < rounds) {
            unsigned long long kk = s_wkey[lane];
            int n_w = (int)(0xFFFFFFFFu - (unsigned)(kk & 0xFFFFFFFFull));
            float alv = __uint_as_float((unsigned)(kk >> 32));
            emit_claim(base + n_w, g, alv, s_wov[lane]);
        }
    }

    // zero-pad: remaining winners = lowest-index zero-align anchors (global order)
    int Z = TOPK_ - rounds;
    if (Z > 0) {
        int cutoff = -1;
        if (lane == 0) {
            int cum = 0;
            #pragma unroll 1
            for (int w = 0; w < 16; w++) {
                unsigned z = ~s_bm[w];
                int c = __popc(z);
                if (cum + c >= Z) {
                    int need = Z - cum;
                    while (true) {
                        int bit = __ffs(z) - 1;
                        if (--need == 0) { cutoff = w*32 + bit; break; }
                        z &= z - 1;
                    }
                    break;
                }
                cum += c;
            }
        }
        cutoff = __shfl_sync(0xffffffffu, cutoff, 0);
        int Bc = min(s_bcnt, B_CAP);
        for (int i = lane; i < Bc; i += 32) {
            int n_w = s_bidx[i];
            if (n_w <= cutoff)
                emit_claim(base + n_w, g, 0.f, s_bov[i]);
        }
    }
}

// ---------------- K2: per-anchor resolve + outputs + row maxima (lazy GTC) ----------------
__global__ void __launch_bounds__(256) k2_resolve(
    const float* __restrict__ pd_scores, const float* __restrict__ pd_bboxes,
    const int* __restrict__ gt_labels,  const float* __restrict__ gt_bboxes,
    const float* __restrict__ mask_gt,  const float* __restrict__ gt_kkpts,
    const float* __restrict__ pd_kkpts, const float* __restrict__ sigma,
    const int* __restrict__ regmax_p,
    float* __restrict__ o_tlabels, float* __restrict__ o_tbboxes,
    float* __restrict__ o_fg, float* __restrict__ o_tgi)
{
    __shared__ GTC s_gt[NMAX];
    int b = blockIdx.y;
    int tid = threadIdx.x;
    int n = blockIdx.x * 256 + tid;
    bool active = (n < NA);
    size_t i = (size_t)b * NA + (active ? n : 0);

    unsigned c = 0u;
    if (active) { c = g_cnt[i]; g_cnt[i] = 0u; }   // reset for next graph replay
    float fg = 0.f, al = 0.f, ovown = 0.f;
    int owner = 0;

    if (active && c == 1u) {
        uint4 cl = g_claim[i];
        owner = (int)cl.x;
        al    = __uint_as_float(cl.y);
        ovown = __uint_as_float(cl.z);
        fg = 1.f;
    }

    bool multi = active && (c > 1u);
    if (__syncthreads_or((int)multi)) {
        if (tid < NMAX) make_gtc(s_gt[tid], gt_bboxes, gt_labels, mask_gt, gt_kkpts, b*NMAX + tid);
        __syncthreads();
        if (multi) {
            float rmf = parse_rmf(regmax_p);
            float rmscale = (rmf - 1.f) * 2.f;
            float sg = sigma[0];
            float fs2 = (2.f*sg)*(2.f*sg);
            float ax, ay, aps;
            anchor_decode(n, rmscale, ax, ay, aps);
            float4 box = ((const float4*)pd_bboxes)[i];
            float atn = pd_atan(box);
            float pkx = pd_kkpts[i*3], pky = pd_kkpts[i*3+1];
            float bv = -1.f; int bgi = 0;
            for (int gg = 0; gg < NMAX; gg++) {
                const GTC& gc = s_gt[gg];
                float ov = 0.f;
                if (gc.valid != 0.f) {
                    float din = fminf(fminf(ax - gc.gx1, ay - gc.gy1),
                                      fminf(gc.gx2 - ax, gc.gy2 - ay));
                    if ((din > EPS) && ((aps - gc.gt_size) >= EPS))
                        ov = eval_overlap(gc, box, atn, pkx, pky, fs2);
                }
                if (ov > bv) { bv = ov; bgi = gg; }
            }
            owner = bgi; ovown = bv; fg = 1.f;
            const GTC& go = s_gt[owner];
            float din = fminf(fminf(ax - go.gx1, ay - go.gy1),
                              fminf(go.gx2 - ax, go.gy2 - ay));
            float m = ((go.valid != 0.f) && (din > EPS) && ((aps - go.gt_size) >= EPS)) ? 1.f : 0.f;
            float score = pd_scores[i * NC + go.lbl] * m;
            al = score * powf(ovown, 6.0f);
            if (al < FLT_MIN_NORMAL) al = 0.f;
        }
    }
    if (!active) return;

    int lbl = __ldg(&gt_labels[b * NMAX + owner]); if (lbl < 0) lbl = 0;
    o_tlabels[i] = (float)lbl;
    ((float4*)o_tbboxes)[i] = __ldg(&((const float4*)gt_bboxes)[b * NMAX + owner]);
    o_fg[i]  = fg;
    o_tgi[i] = (float)owner;
    g_anchor_al[i] = al;
    if (fg > 0.f) {
        atomicMax(&g_posalign[b*NMAX + owner], __float_as_uint(al));
        atomicMax(&g_posov   [b*NMAX + owner], __float_as_uint(ovown));
    }
}

// ---------------- K3: two-phase — coalesced per-anchor compute, then coalesced row writes ----------------
// BS*NA = 134400 = 525 * 256 exactly; each block owns 256 consecutive anchors.
__global__ void __launch_bounds__(256) k3_scores(
    const float* __restrict__ o_tlabels, const float* __restrict__ o_fg,
    const float* __restrict__ o_tgi, float* __restrict__ o_tscores)
{
    __shared__ int   s_lbl[256];
    __shared__ float s_val[256];

    int tid  = threadIdx.x;
    int abase = blockIdx.x * 256;
    int i = abase + tid;
    int b = i / NA;

    // phase 1: coalesced loads, per-anchor value
    float fg  = o_fg[i];
    int   lbl = (int)o_tlabels[i];
    float val = 0.f;
    if (fg > 0.f) {
        int owner = (int)o_tgi[i];
        float al = g_anchor_al[i];
        float po = __uint_as_float(g_posov[b*NMAX + owner]);
        float pa = __uint_as_float(g_posalign[b*NMAX + owner]);
        val = al * po / (pa + EPS);
    }
    s_lbl[tid] = lbl;
    s_val[tid] = val;
    __syncthreads();

    // phase 2: write the block's 256x80 output slice, fully coalesced STG.128
    float4* outp = (float4*)(o_tscores + (size_t)abase * NC);   // 5120 float4s
    #pragma unroll
    for (int k = 0; k < 20; k++) {
        int f  = tid + 256 * k;        // consecutive lanes -> consecutive float4s
        int a  = f / 20;               // anchor within block
        int c4 = f - a * 20;           // float4 column
        int la = s_lbl[a];
        float va = s_val[a];
        int base4 = c4 * 4;
        float4 v;
        v.x = (la == base4 + 0) ? va : 0.f;
        v.y = (la == base4 + 1) ? va : 0.f;
        v.z = (la == base4 + 2) ? va : 0.f;
        v.w = (la == base4 + 3) ? va : 0.f;
        outp[f] = v;
    }
}

// ---------------- host ----------------
extern "C" void kernel_launch(void* const* d_in, const int* in_sizes, int n_in,
                              void* d_out, int out_size)
{
    const float* pd_scores = (const float*)d_in[0];
    const float* pd_bboxes = (const float*)d_in[1];
    const int*   gt_labels = (const int*)  d_in[3];
    const float* gt_bboxes = (const float*)d_in[4];
    const float* mask_gt   = (const float*)d_in[5];
    const float* gt_kkpts  = (const float*)d_in[6];
    const float* pd_kkpts  = (const float*)d_in[7];
    const float* sigma     = (const float*)d_in[8];
    const int*   regmax    = (n_in > 10) ? (const int*)d_in[10] : nullptr;

    float* out       = (float*)d_out;
    float* o_tlabels = out;
    float* o_tbboxes = out + (size_t)BS*NA;
    float* o_tscores = out + (size_t)BS*NA*5;
    float* o_fg      = out + (size_t)BS*NA*(5 + NC);
    float* o_tgi     = out + (size_t)BS*NA*(6 + NC);

    k1_metrics<<<BS*NMAX, NT1>>>(pd_scores, pd_bboxes, gt_labels, gt_bboxes,
                                 mask_gt, gt_kkpts, pd_kkpts, sigma, regmax);
    {
        dim3 grid((NA + 255)/256, BS);
        k2_resolve<<<grid, 256>>>(pd_scores, pd_bboxes, gt_labels, gt_bboxes,
                                  mask_gt, gt_kkpts, pd_kkpts, sigma, regmax,
                                  o_tlabels, o_tbboxes, o_fg, o_tgi);
    }
    k3_scores <<<(BS*NA)/256, 256>>>(o_tlabels, o_fg, o_tgi, o_tscores);
}

// round 15
// speedup vs baseline: 1.4357x; 1.0009x over previous
#include <cuda_runtime.h>
#include <math_constants.h>
#include <math.h>

#define BS    16
#define NMAX  64
#define NA    8400
#define NC    80
#define TOPK_ 13
#define EPS   1e-9f
#define CEPS  1e-7f
#define FLT_MIN_NORMAL 1.17549435e-38f
#define P_CAP 320    // in-box candidates <= 15^2+8^2+4^2 = 305
#define B_CAP 320
#define NT1   128

// ---------------- persistent scratch (small) ----------------
__device__ unsigned int g_cnt   [BS*NA];     // zero at load; k2 re-zeroes after read
__device__ uint4        g_claim [BS*NA];     // k1: {g, align, overlap, 0} ; k2 rewrites: {owner, align, overlap, fg}
__device__ unsigned int g_posalign[BS*NMAX]; // float bits (nonneg)
__device__ unsigned int g_posov   [BS*NMAX];

// analytic anchor grid (bitwise-equal to reference's (i+0.5)*s construction)
__device__ __forceinline__ void anchor_decode(int n, float rmscale,
                                              float& ax, float& ay, float& aps) {
    if (n < 6400)      { int r = n / 80;        int c = n - r*80;        ax = (c+0.5f)*8.f;  ay = (r+0.5f)*8.f;  aps = 8.f*rmscale;  }
    else if (n < 8000) { int r = (n-6400) / 40; int c = (n-6400) - r*40; ax = (c+0.5f)*16.f; ay = (r+0.5f)*16.f; aps = 16.f*rmscale; }
    else               { int r = (n-8000) / 20; int c = (n-8000) - r*20; ax = (c+0.5f)*32.f; ay = (r+0.5f)*32.f; aps = 32.f*rmscale; }
}

struct GTC {
    float gx1, gy1, gx2, gy2;
    float w1h1, atan1, gsx, gsy;
    float gt_size, areap, kx, ky;
    float kmask, kden, valid;
    int   lbl;
};

__device__ __forceinline__ void make_gtc(GTC& g, const float* gt_bboxes,
                                         const int* gt_labels, const float* mask_gt,
                                         const float* gt_kkpts, int bg) {
    float gx1 = gt_bboxes[bg*4+0], gy1 = gt_bboxes[bg*4+1];
    float gx2 = gt_bboxes[bg*4+2], gy2 = gt_bboxes[bg*4+3];
    g.gx1 = gx1; g.gy1 = gy1; g.gx2 = gx2; g.gy2 = gy2;
    float w1 = gx2 - gx1, h1 = gy2 - gy1 + CEPS;
    g.atan1 = atanf(w1 / h1);
    g.w1h1  = w1 * h1;
    g.gsx = gx1 + gx2; g.gsy = gy1 + gy2;
    float gw = gx2 - gx1, gh = gy2 - gy1;
    g.gt_size = 0.5f * (gw + gh);
    g.areap   = gw * gh * 0.53f + 1e-7f;
    g.kx = gt_kkpts[bg*3+0]; g.ky = gt_kkpts[bg*3+1];
    float kv = gt_kkpts[bg*3+2];
    g.kmask = (kv != 0.f) ? 1.f : 0.f;
    g.kden  = g.kmask + 1e-7f;
    g.valid = mask_gt[bg];
    g.lbl   = gt_labels[bg];
}

// overlap for an m==1 cell; same arithmetic sequence as all passing rounds
__device__ __forceinline__ float eval_overlap(const GTC& g, float4 box, float atn,
                                              float pkx, float pky, float fs2) {
    const float inv_pi2_4 = 0.4052847345693511f;
    float px1 = box.x, py1 = box.y, px2 = box.z, py2 = box.w;
    float w2 = px2 - px1, h2 = py2 - py1 + CEPS;
    float iw = fminf(g.gx2, px2) - fmaxf(g.gx1, px1);
    float ih = fminf(g.gy2, py2) - fmaxf(g.gy1, py1);
    float inter = fmaxf(iw, 0.f) * fmaxf(ih, 0.f);
    float uni = g.w1h1 + w2 * h2 - inter + CEPS;
    float iou = inter / uni;
    float cw = fmaxf(g.gx2, px2) - fminf(g.gx1, px1);
    float ch = fmaxf(g.gy2, py2) - fminf(g.gy1, py1);
    float c2 = cw*cw + ch*ch + CEPS;
    float dx = px1 + px2 - g.gsx, dy = py1 + py2 - g.gsy;
    float rho2 = (dx*dx + dy*dy) / 4.0f;
    float dat = atn - g.atan1;
    float v = inv_pi2_4 * (dat * dat);
    float a = v / (v - iou + (1.f + CEPS));
    float cio = iou - (rho2 / c2 + v * a);
    cio = fmaxf(cio, 0.f);
    float ddx = pkx - g.kx, ddy = pky - g.ky;
    float d2 = ddx*ddx + ddy*ddy;
    float e = d2 / fs2 / g.areap / 2.0f;
    float kio = (expf(-e) * g.kmask) / g.kden;
    float overlap = (cio + kio) / 2.0f;
    if (overlap < FLT_MIN_NORMAL) overlap = 0.f;   // FTZ (matches reference)
    return overlap;
}

__device__ __forceinline__ float parse_rmf(const int* regmax_p) {
    float rmf = 16.f;
    if (regmax_p) {
        int v = regmax_p[0];
        if (v >= 1 && v <= 65536) rmf = (float)v;
        else { float fv = __int_as_float(v); if (fv >= 1.f && fv <= 65536.f) rmf = fv; }
    }
    return rmf;
}

__device__ __forceinline__ float pd_atan(float4 box) {
    float w2 = box.z - box.x;
    float h2 = box.w - box.y + CEPS;
    return atanf(w2 / h2);
}

// race-safe claim: plain STG.128 + RED.ADD; data only trusted when final cnt==1
__device__ __forceinline__ void emit_claim(size_t idx, int g, float alv, float ov) {
    g_claim[idx] = make_uint4((unsigned)g, __float_as_uint(alv), __float_as_uint(ov), 0u);
    atomicAdd(&g_cnt[idx], 1u);
}

// ---------------- K1: block-per-gt build + adaptive top-13 ----------------
__global__ void __launch_bounds__(NT1) k1_metrics(
    const float* __restrict__ pd_scores, const float* __restrict__ pd_bboxes,
    const int* __restrict__ gt_labels,  const float* __restrict__ gt_bboxes,
    const float* __restrict__ mask_gt,  const float* __restrict__ gt_kkpts,
    const float* __restrict__ pd_kkpts, const float* __restrict__ sigma,
    const int* __restrict__ regmax_p)
{
    __shared__ unsigned long long s_pkey[P_CAP];
    __shared__ float s_pov[P_CAP];
    __shared__ int   s_bidx[B_CAP];
    __shared__ float s_bov[B_CAP];
    __shared__ unsigned int s_bm[16];   // 512-bit bitmap (cutoff < 512 provably)
    __shared__ int s_pcnt, s_bcnt;
    __shared__ unsigned long long s_wkey[TOPK_];
    __shared__ float s_wov[TOPK_];

    int bg = blockIdx.x;
    int b  = bg >> 6;
    int g  = bg & 63;
    int tid = threadIdx.x;

    float mgt = __ldg(&mask_gt[bg]);    // issue early (independent of inits)
    if (tid == 0) { g_posalign[bg] = 0u; g_posov[bg] = 0u; s_pcnt = 0; s_bcnt = 0; }
    if (tid < 16) s_bm[tid] = 0u;
    __syncthreads();
    if (mgt == 0.f) return;

    float rmf = parse_rmf(regmax_p);
    float rmscale = (rmf - 1.f) * 2.f;
    float sg = sigma[0];
    float fs2 = (2.f*sg)*(2.f*sg);

    GTC gc; make_gtc(gc, gt_bboxes, gt_labels, mask_gt, gt_kkpts, bg);

    const float4* pb = (const float4*)(pd_bboxes + (size_t)b * NA * 4);
    const float*  ps = pd_scores + (size_t)b * NA * NC + gc.lbl;
    const float*  pk = pd_kkpts  + (size_t)b * NA * 3;

    const int   L_base[3] = {0, 6400, 8000};
    const int   L_W[3]    = {80, 40, 20};
    const float L_s[3]    = {8.f, 16.f, 32.f};

    #pragma unroll
    for (int l = 0; l < 3; l++) {
        float s = L_s[l];
        float aps = s * rmscale;
        if (!((aps - gc.gt_size) >= EPS)) continue;
        int W = L_W[l];
        float inv_s = 1.f / s;
        int c_lo = max(0,     (int)floorf(gc.gx1 * inv_s - 0.5f) - 1);
        int c_hi = min(W - 1, (int)floorf(gc.gx2 * inv_s - 0.5f) + 1);
        int r_lo = max(0,     (int)floorf(gc.gy1 * inv_s - 0.5f) - 1);
        int r_hi = min(W - 1, (int)floorf(gc.gy2 * inv_s - 0.5f) + 1);
        int ncc = c_hi - c_lo + 1, nrr = r_hi - r_lo + 1;
        if (ncc <= 0 || nrr <= 0) continue;
        int tot = ncc * nrr;
        for (int j = tid; j < tot; j += NT1) {
            int r = r_lo + j / ncc, c = c_lo + j % ncc;
            float ax = (c + 0.5f) * s, ay = (r + 0.5f) * s;
            float din = fminf(fminf(ax - gc.gx1, ay - gc.gy1),
                              fminf(gc.gx2 - ax, gc.gy2 - ay));
            if (!(din > EPS)) continue;          // exact in-box test
            int n = L_base[l] + r * W + c;

            float4 box = pb[n];
            float atn = pd_atan(box);
            float pkx = pk[3*n], pky = pk[3*n+1];
            float overlap = eval_overlap(gc, box, atn, pkx, pky, fs2);
            float score = ps[(size_t)n * NC];
            float alv = score * powf(overlap, 6.0f);
            if (alv < FLT_MIN_NORMAL) alv = 0.f;  // FTZ (matches reference)

            if (alv > 0.f) {
                int slot = atomicAdd(&s_pcnt, 1);
                if (slot < P_CAP) {
                    s_pkey[slot] = ((unsigned long long)__float_as_uint(alv) << 32)
                                 | (unsigned long long)(0xFFFFFFFFu - (unsigned)n);
                    s_pov[slot] = overlap;
                }
                if (n < 512) atomicOr(&s_bm[n >> 5], 1u << (n & 31));
            } else {
                int slot = atomicAdd(&s_bcnt, 1);
                if (slot < B_CAP) { s_bidx[slot] = n; s_bov[slot] = overlap; }
            }
        }
    }
    __syncthreads();

    // ---- warp 0 only: adaptive selection ----
    if (tid >= 32) return;
    int lane = tid;
    int P = min(s_pcnt, P_CAP);
    size_t base = (size_t)b * NA;
    int rounds;

    if (P <= TOPK_) {
        rounds = P;
        if (lane < P) {
            unsigned long long kk = s_pkey[lane];
            int n_w = (int)(0xFFFFFFFFu - (unsigned)(kk & 0xFFFFFFFFull));
            float alv = __uint_as_float((unsigned)(kk >> 32));
            emit_claim(base + n_w, g, alv, s_pov[lane]);
        }
    } else if (P <= 32) {
        rounds = TOPK_;
        unsigned long long key = (lane < P) ? s_pkey[lane] : 0ull;
        int slot = lane;
        #pragma unroll
        for (int kk2 = 2; kk2 <= 32; kk2 <<= 1) {
            #pragma unroll
            for (int j = kk2 >> 1; j > 0; j >>= 1) {
                unsigned long long pkk = __shfl_xor_sync(0xffffffffu, key, j);
                int psl = __shfl_xor_sync(0xffffffffu, slot, j);
                bool lower = (lane & j) == 0;
                bool desc  = (lane & kk2) == 0;
                bool takeMax = (desc == lower);
                bool sw = takeMax ? (pkk > key) : (pkk < key);
                if (sw) { key = pkk; slot = psl; }
            }
        }
        if (lane < TOPK_) {
            int n_w = (int)(0xFFFFFFFFu - (unsigned)(key & 0xFFFFFFFFull));
            float alv = __uint_as_float((unsigned)(key >> 32));
            emit_claim(base + n_w, g, alv, s_pov[slot]);
        }
    } else {
        unsigned long long cur = 0ull; int curs = -1;
        for (int i = lane; i < P; i += 32) {
            unsigned long long kk = s_pkey[i];
            if (kk > cur) { cur = kk; curs = i; }
        }
        rounds = 0;
        #pragma unroll 1
        for (int k = 0; k < TOPK_; k++) {
            unsigned long long bk = cur;
            #pragma unroll
            for (int o = 16; o > 0; o >>= 1) {
                unsigned long long ok = __shfl_xor_sync(0xffffffffu, bk, o);
                if (ok > bk) bk = ok;
            }
            unsigned won = __ballot_sync(0xffffffffu, cur == bk);  // keys unique
            int bl = __ffs(won) - 1;
            if (lane == bl) {
                s_wkey[k] = bk; s_wov[k] = s_pov[curs];
                s_pkey[curs] = 0ull;
                cur = 0ull; curs = -1;
                for (int i = lane; i < P; i += 32) {
                    unsigned long long kk = s_pkey[i];
                    if (kk > cur) { cur = kk; curs = i; }
                }
            }
            rounds++;
        }
        __syncwarp();
        if (lane < rounds) {
            unsigned long long kk = s_wkey[lane];
            int n_w = (int)(0xFFFFFFFFu - (unsigned)(kk & 0xFFFFFFFFull));
            float alv = __uint_as_float((unsigned)(kk >> 32));
            emit_claim(base + n_w, g, alv, s_wov[lane]);
        }
    }

    // zero-pad: remaining winners = lowest-index zero-align anchors (global order)
    int Z = TOPK_ - rounds;
    if (Z > 0) {
        int cutoff = -1;
        if (lane == 0) {
            int cum = 0;
            #pragma unroll 1
            for (int w = 0; w < 16; w++) {
                unsigned z = ~s_bm[w];
                int c = __popc(z);
                if (cum + c >= Z) {
                    int need = Z - cum;
                    while (true) {
                        int bit = __ffs(z) - 1;
                        if (--need == 0) { cutoff = w*32 + bit; break; }
                        z &= z - 1;
                    }
                    break;
                }
                cum += c;
            }
        }
        cutoff = __shfl_sync(0xffffffffu, cutoff, 0);
        int Bc = min(s_bcnt, B_CAP);
        for (int i = lane; i < Bc; i += 32) {
            int n_w = s_bidx[i];
            if (n_w <= cutoff)
                emit_claim(base + n_w, g, 0.f, s_bov[i]);
        }
    }
}

// ---------------- K2: pure resolver — rewrite g_claim as {owner, al, ov, fg} + row maxima ----------------
__global__ void __launch_bounds__(256) k2_resolve(
    const float* __restrict__ pd_scores, const float* __restrict__ pd_bboxes,
    const int* __restrict__ gt_labels,  const float* __restrict__ gt_bboxes,
    const float* __restrict__ mask_gt,  const float* __restrict__ gt_kkpts,
    const float* __restrict__ pd_kkpts, const float* __restrict__ sigma,
    const int* __restrict__ regmax_p)
{
    __shared__ GTC s_gt[NMAX];
    int b = blockIdx.y;
    int tid = threadIdx.x;
    int n = blockIdx.x * 256 + tid;
    bool active = (n < NA);
    size_t i = (size_t)b * NA + (active ? n : 0);

    unsigned c = 0u;
    if (active) { c = g_cnt[i]; g_cnt[i] = 0u; }   // reset for next graph replay
    float fg = 0.f, al = 0.f, ovown = 0.f;
    int owner = 0;

    if (active && c == 1u) {
        uint4 cl = g_claim[i];
        owner = (int)cl.x;
        al    = __uint_as_float(cl.y);
        ovown = __uint_as_float(cl.z);
        fg = 1.f;
    }

    bool multi = active && (c > 1u);
    if (__syncthreads_or((int)multi)) {
        if (tid < NMAX) make_gtc(s_gt[tid], gt_bboxes, gt_labels, mask_gt, gt_kkpts, b*NMAX + tid);
        __syncthreads();
        if (multi) {
            float rmf = parse_rmf(regmax_p);
            float rmscale = (rmf - 1.f) * 2.f;
            float sg = sigma[0];
            float fs2 = (2.f*sg)*(2.f*sg);
            float ax, ay, aps;
            anchor_decode(n, rmscale, ax, ay, aps);
            float4 box = ((const float4*)pd_bboxes)[i];
            float atn = pd_atan(box);
            float pkx = pd_kkpts[i*3], pky = pd_kkpts[i*3+1];
            float bv = -1.f; int bgi = 0;
            for (int gg = 0; gg < NMAX; gg++) {
                const GTC& gc = s_gt[gg];
                float ov = 0.f;
                if (gc.valid != 0.f) {
                    float din = fminf(fminf(ax - gc.gx1, ay - gc.gy1),
                                      fminf(gc.gx2 - ax, gc.gy2 - ay));
                    if ((din > EPS) && ((aps - gc.gt_size) >= EPS))
                        ov = eval_overlap(gc, box, atn, pkx, pky, fs2);
                }
                if (ov > bv) { bv = ov; bgi = gg; }
            }
            owner = bgi; ovown = bv; fg = 1.f;
            const GTC& go = s_gt[owner];
            float din = fminf(fminf(ax - go.gx1, ay - go.gy1),
                              fminf(go.gx2 - ax, go.gy2 - ay));
            float m = ((go.valid != 0.f) && (din > EPS) && ((aps - go.gt_size) >= EPS)) ? 1.f : 0.f;
            float score = pd_scores[i * NC + go.lbl] * m;
            al = score * powf(ovown, 6.0f);
            if (al < FLT_MIN_NORMAL) al = 0.f;
        }
    }
    if (!active) return;

    // coalesced resolved record; k3 is the single output writer
    g_claim[i] = make_uint4((unsigned)owner, __float_as_uint(al),
                            __float_as_uint(ovown), (fg > 0.f) ? 1u : 0u);
    if (fg > 0.f) {
        atomicMax(&g_posalign[b*NMAX + owner], __float_as_uint(al));
        atomicMax(&g_posov   [b*NMAX + owner], __float_as_uint(ovown));
    }
}

// ---------------- K3: single output writer (all five outputs, coalesced) ----------------
// BS*NA = 134400 = 525 * 256 exactly; each block owns 256 consecutive anchors.
__global__ void __launch_bounds__(256) k3_outputs(
    const int* __restrict__ gt_labels, const float* __restrict__ gt_bboxes,
    float* __restrict__ o_tlabels, float* __restrict__ o_tbboxes,
    float* __restrict__ o_fg, float* __restrict__ o_tgi,
    float* __restrict__ o_tscores)
{
    __shared__ int   s_lbl[256];
    __shared__ float s_val[256];

    int tid  = threadIdx.x;
    int abase = blockIdx.x * 256;
    int i = abase + tid;
    int b = i / NA;

    // phase 1: coalesced resolved record + tiny L2-hot gt gathers
    uint4 cl = g_claim[i];
    int   owner = (int)cl.x;
    float al    = __uint_as_float(cl.y);
    unsigned fgu = cl.w;

    float val = 0.f;
    if (fgu) {
        float po = __uint_as_float(g_posov[b*NMAX + owner]);
        float pa = __uint_as_float(g_posalign[b*NMAX + owner]);
        val = al * po / (pa + EPS);
    }
    int lbl = __ldg(&gt_labels[b * NMAX + owner]); if (lbl < 0) lbl = 0;

    o_tlabels[i] = (float)lbl;
    ((float4*)o_tbboxes)[i] = __ldg(&((const float4*)gt_bboxes)[b * NMAX + owner]);
    o_fg[i]  = fgu ? 1.f : 0.f;
    o_tgi[i] = (float)owner;

    s_lbl[tid] = lbl;
    s_val[tid] = val;
    __syncthreads();

    // phase 2: write the block's 256x80 tscores slice, fully coalesced STG.128
    float4* outp = (float4*)(o_tscores + (size_t)abase * NC);   // 5120 float4s
    #pragma unroll
    for (int k = 0; k < 20; k++) {
        int f  = tid + 256 * k;        // consecutive lanes -> consecutive float4s
        int a  = f / 20;               // anchor within block
        int c4 = f - a * 20;           // float4 column
        int la = s_lbl[a];
        float va = s_val[a];
        int base4 = c4 * 4;
        float4 v;
        v.x = (la == base4 + 0) ? va : 0.f;
        v.y = (la == base4 + 1) ? va : 0.f;
        v.z = (la == base4 + 2) ? va : 0.f;
        v.w = (la == base4 + 3) ? va : 0.f;
        outp[f] = v;
    }
}

// ---------------- host ----------------
extern "C" void kernel_launch(void* const* d_in, const int* in_sizes, int n_in,
                              void* d_out, int out_size)
{
    const float* pd_scores = (const float*)d_in[0];
    const float* pd_bboxes = (const float*)d_in[1];
    const int*   gt_labels = (const int*)  d_in[3];
    const float* gt_bboxes = (const float*)d_in[4];
    const float* mask_gt   = (const float*)d_in[5];
    const float* gt_kkpts  = (const float*)d_in[6];
    const float* pd_kkpts  = (const float*)d_in[7];
    const float* sigma     = (const float*)d_in[8];
    const int*   regmax    = (n_in > 10) ? (const int*)d_in[10] : nullptr;

    float* out       = (float*)d_out;
    float* o_tlabels = out;
    float* o_tbboxes = out + (size_t)BS*NA;
    float* o_tscores = out + (size_t)BS*NA*5;
    float* o_fg      = out + (size_t)BS*NA*(5 + NC);
    float* o_tgi     = out + (size_t)BS*NA*(6 + NC);

    k1_metrics<<<BS*NMAX, NT1>>>(pd_scores, pd_bboxes, gt_labels, gt_bboxes,
                                 mask_gt, gt_kkpts, pd_kkpts, sigma, regmax);
    {
        dim3 grid((NA + 255)/256, BS);
        k2_resolve<<<grid, 256>>>(pd_scores, pd_bboxes, gt_labels, gt_bboxes,
                                  mask_gt, gt_kkpts, pd_kkpts, sigma, regmax);
    }
    k3_outputs<<<(BS*NA)/256, 256>>>(gt_labels, gt_bboxes,
                                     o_tlabels, o_tbboxes, o_fg, o_tgi, o_tscores);
}

// round 16
// speedup vs baseline: 1.5295x; 1.0653x over previous
#include <cuda_runtime.h>
#include <math_constants.h>
#include <math.h>

#define BS    16
#define NMAX  64
#define NA    8400
#define NC    80
#define TOPK_ 13
#define EPS   1e-9f
#define CEPS  1e-7f
#define FLT_MIN_NORMAL 1.17549435e-38f
#define P_CAP 320    // in-box candidates <= 15^2+8^2+4^2 = 305
#define B_CAP 320
#define NT1   128
#define POS_MAX 16384   // >= 1024 gts * 13 winners

// ---------------- persistent scratch (small) ----------------
__device__ unsigned int g_cnt   [BS*NA];     // zero at load; k2 re-zeroes after read
__device__ uint4        g_claim [BS*NA];     // k1: {g, align, overlap, 0}
__device__ unsigned int g_posalign[BS*NMAX]; // float bits (nonneg)
__device__ unsigned int g_posov   [BS*NMAX];
__device__ int          g_poscnt;            // fg>0 list counter (k1 resets)
__device__ uint4        g_poslist[POS_MAX];  // {i, b*NMAX+owner, align_bits, lbl}

// analytic anchor grid (bitwise-equal to reference's (i+0.5)*s construction)
__device__ __forceinline__ void anchor_decode(int n, float rmscale,
                                              float& ax, float& ay, float& aps) {
    if (n < 6400)      { int r = n / 80;        int c = n - r*80;        ax = (c+0.5f)*8.f;  ay = (r+0.5f)*8.f;  aps = 8.f*rmscale;  }
    else if (n < 8000) { int r = (n-6400) / 40; int c = (n-6400) - r*40; ax = (c+0.5f)*16.f; ay = (r+0.5f)*16.f; aps = 16.f*rmscale; }
    else               { int r = (n-8000) / 20; int c = (n-8000) - r*20; ax = (c+0.5f)*32.f; ay = (r+0.5f)*32.f; aps = 32.f*rmscale; }
}

struct GTC {
    float gx1, gy1, gx2, gy2;
    float w1h1, atan1, gsx, gsy;
    float gt_size, areap, kx, ky;
    float kmask, kden, valid;
    int   lbl;
};

__device__ __forceinline__ void make_gtc(GTC& g, const float* gt_bboxes,
                                         const int* gt_labels, const float* mask_gt,
                                         const float* gt_kkpts, int bg) {
    float gx1 = gt_bboxes[bg*4+0], gy1 = gt_bboxes[bg*4+1];
    float gx2 = gt_bboxes[bg*4+2], gy2 = gt_bboxes[bg*4+3];
    g.gx1 = gx1; g.gy1 = gy1; g.gx2 = gx2; g.gy2 = gy2;
    float w1 = gx2 - gx1, h1 = gy2 - gy1 + CEPS;
    g.atan1 = atanf(w1 / h1);
    g.w1h1  = w1 * h1;
    g.gsx = gx1 + gx2; g.gsy = gy1 + gy2;
    float gw = gx2 - gx1, gh = gy2 - gy1;
    g.gt_size = 0.5f * (gw + gh);
    g.areap   = gw * gh * 0.53f + 1e-7f;
    g.kx = gt_kkpts[bg*3+0]; g.ky = gt_kkpts[bg*3+1];
    float kv = gt_kkpts[bg*3+2];
    g.kmask = (kv != 0.f) ? 1.f : 0.f;
    g.kden  = g.kmask + 1e-7f;
    g.valid = mask_gt[bg];
    g.lbl   = gt_labels[bg];
}

// overlap for an m==1 cell; same arithmetic sequence as all passing rounds
__device__ __forceinline__ float eval_overlap(const GTC& g, float4 box, float atn,
                                              float pkx, float pky, float fs2) {
    const float inv_pi2_4 = 0.4052847345693511f;
    float px1 = box.x, py1 = box.y, px2 = box.z, py2 = box.w;
    float w2 = px2 - px1, h2 = py2 - py1 + CEPS;
    float iw = fminf(g.gx2, px2) - fmaxf(g.gx1, px1);
    float ih = fminf(g.gy2, py2) - fmaxf(g.gy1, py1);
    float inter = fmaxf(iw, 0.f) * fmaxf(ih, 0.f);
    float uni = g.w1h1 + w2 * h2 - inter + CEPS;
    float iou = inter / uni;
    float cw = fmaxf(g.gx2, px2) - fminf(g.gx1, px1);
    float ch = fmaxf(g.gy2, py2) - fminf(g.gy1, py1);
    float c2 = cw*cw + ch*ch + CEPS;
    float dx = px1 + px2 - g.gsx, dy = py1 + py2 - g.gsy;
    float rho2 = (dx*dx + dy*dy) / 4.0f;
    float dat = atn - g.atan1;
    float v = inv_pi2_4 * (dat * dat);
    float a = v / (v - iou + (1.f + CEPS));
    float cio = iou - (rho2 / c2 + v * a);
    cio = fmaxf(cio, 0.f);
    float ddx = pkx - g.kx, ddy = pky - g.ky;
    float d2 = ddx*ddx + ddy*ddy;
    float e = d2 / fs2 / g.areap / 2.0f;
    float kio = (expf(-e) * g.kmask) / g.kden;
    float overlap = (cio + kio) / 2.0f;
    if (overlap < FLT_MIN_NORMAL) overlap = 0.f;   // FTZ (matches reference)
    return overlap;
}

__device__ __forceinline__ float parse_rmf(const int* regmax_p) {
    float rmf = 16.f;
    if (regmax_p) {
        int v = regmax_p[0];
        if (v >= 1 && v <= 65536) rmf = (float)v;
        else { float fv = __int_as_float(v); if (fv >= 1.f && fv <= 65536.f) rmf = fv; }
    }
    return rmf;
}

__device__ __forceinline__ float pd_atan(float4 box) {
    float w2 = box.z - box.x;
    float h2 = box.w - box.y + CEPS;
    return atanf(w2 / h2);
}

// race-safe claim: plain STG.128 + RED.ADD; data only trusted when final cnt==1
__device__ __forceinline__ void emit_claim(size_t idx, int g, float alv, float ov) {
    g_claim[idx] = make_uint4((unsigned)g, __float_as_uint(alv), __float_as_uint(ov), 0u);
    atomicAdd(&g_cnt[idx], 1u);
}

// ---------------- K1: block-per-gt build + adaptive top-13 ----------------
__global__ void __launch_bounds__(NT1) k1_metrics(
    const float* __restrict__ pd_scores, const float* __restrict__ pd_bboxes,
    const int* __restrict__ gt_labels,  const float* __restrict__ gt_bboxes,
    const float* __restrict__ mask_gt,  const float* __restrict__ gt_kkpts,
    const float* __restrict__ pd_kkpts, const float* __restrict__ sigma,
    const int* __restrict__ regmax_p)
{
    __shared__ unsigned long long s_pkey[P_CAP];
    __shared__ float s_pov[P_CAP];
    __shared__ int   s_bidx[B_CAP];
    __shared__ float s_bov[B_CAP];
    __shared__ unsigned int s_bm[16];   // 512-bit bitmap (cutoff < 512 provably)
    __shared__ int s_pcnt, s_bcnt;
    __shared__ unsigned long long s_wkey[TOPK_];
    __shared__ float s_wov[TOPK_];

    int bg = blockIdx.x;
    int b  = bg >> 6;
    int g  = bg & 63;
    int tid = threadIdx.x;

    float mgt = __ldg(&mask_gt[bg]);    // issue early (independent of inits)
    if (tid == 0) { g_posalign[bg] = 0u; g_posov[bg] = 0u; s_pcnt = 0; s_bcnt = 0; }
    if (tid < 16) s_bm[tid] = 0u;
    if (bg == 0 && tid == 0) g_poscnt = 0;   // reset fg>0 list for this replay
    __syncthreads();
    if (mgt == 0.f) return;

    float rmf = parse_rmf(regmax_p);
    float rmscale = (rmf - 1.f) * 2.f;
    float sg = sigma[0];
    float fs2 = (2.f*sg)*(2.f*sg);

    GTC gc; make_gtc(gc, gt_bboxes, gt_labels, mask_gt, gt_kkpts, bg);

    const float4* pb = (const float4*)(pd_bboxes + (size_t)b * NA * 4);
    const float*  ps = pd_scores + (size_t)b * NA * NC + gc.lbl;
    const float*  pk = pd_kkpts  + (size_t)b * NA * 3;

    const int   L_base[3] = {0, 6400, 8000};
    const int   L_W[3]    = {80, 40, 20};
    const float L_s[3]    = {8.f, 16.f, 32.f};

    #pragma unroll
    for (int l = 0; l < 3; l++) {
        float s = L_s[l];
        float aps = s * rmscale;
        if (!((aps - gc.gt_size) >= EPS)) continue;
        int W = L_W[l];
        float inv_s = 1.f / s;
        int c_lo = max(0,     (int)floorf(gc.gx1 * inv_s - 0.5f) - 1);
        int c_hi = min(W - 1, (int)floorf(gc.gx2 * inv_s - 0.5f) + 1);
        int r_lo = max(0,     (int)floorf(gc.gy1 * inv_s - 0.5f) - 1);
        int r_hi = min(W - 1, (int)floorf(gc.gy2 * inv_s - 0.5f) + 1);
        int ncc = c_hi - c_lo + 1, nrr = r_hi - r_lo + 1;
        if (ncc <= 0 || nrr <= 0) continue;
        int tot = ncc * nrr;
        for (int j = tid; j < tot; j += NT1) {
            int r = r_lo + j / ncc, c = c_lo + j % ncc;
            float ax = (c + 0.5f) * s, ay = (r + 0.5f) * s;
            float din = fminf(fminf(ax - gc.gx1, ay - gc.gy1),
                              fminf(gc.gx2 - ax, gc.gy2 - ay));
            if (!(din > EPS)) continue;          // exact in-box test
            int n = L_base[l] + r * W + c;

            float4 box = pb[n];
            float atn = pd_atan(box);
            float pkx = pk[3*n], pky = pk[3*n+1];
            float overlap = eval_overlap(gc, box, atn, pkx, pky, fs2);
            float score = ps[(size_t)n * NC];
            float alv = score * powf(overlap, 6.0f);
            if (alv < FLT_MIN_NORMAL) alv = 0.f;  // FTZ (matches reference)

            if (alv > 0.f) {
                int slot = atomicAdd(&s_pcnt, 1);
                if (slot < P_CAP) {
                    s_pkey[slot] = ((unsigned long long)__float_as_uint(alv) << 32)
                                 | (unsigned long long)(0xFFFFFFFFu - (unsigned)n);
                    s_pov[slot] = overlap;
                }
                if (n < 512) atomicOr(&s_bm[n >> 5], 1u << (n & 31));
            } else {
                int slot = atomicAdd(&s_bcnt, 1);
                if (slot < B_CAP) { s_bidx[slot] = n; s_bov[slot] = overlap; }
            }
        }
    }
    __syncthreads();

    // ---- warp 0 only: adaptive selection ----
    if (tid >= 32) return;
    int lane = tid;
    int P = min(s_pcnt, P_CAP);
    size_t base = (size_t)b * NA;
    int rounds;

    if (P <= TOPK_) {
        rounds = P;
        if (lane < P) {
            unsigned long long kk = s_pkey[lane];
            int n_w = (int)(0xFFFFFFFFu - (unsigned)(kk & 0xFFFFFFFFull));
            float alv = __uint_as_float((unsigned)(kk >> 32));
            emit_claim(base + n_w, g, alv, s_pov[lane]);
        }
    } else if (P <= 32) {
        rounds = TOPK_;
        unsigned long long key = (lane < P) ? s_pkey[lane] : 0ull;
        int slot = lane;
        #pragma unroll
        for (int kk2 = 2; kk2 <= 32; kk2 <<= 1) {
            #pragma unroll
            for (int j = kk2 >> 1; j > 0; j >>= 1) {
                unsigned long long pkk = __shfl_xor_sync(0xffffffffu, key, j);
                int psl = __shfl_xor_sync(0xffffffffu, slot, j);
                bool lower = (lane & j) == 0;
                bool desc  = (lane & kk2) == 0;
                bool takeMax = (desc == lower);
                bool sw = takeMax ? (pkk > key) : (pkk < key);
                if (sw) { key = pkk; slot = psl; }
            }
        }
        if (lane < TOPK_) {
            int n_w = (int)(0xFFFFFFFFu - (unsigned)(key & 0xFFFFFFFFull));
            float alv = __uint_as_float((unsigned)(key >> 32));
            emit_claim(base + n_w, g, alv, s_pov[slot]);
        }
    } else {
        unsigned long long cur = 0ull; int curs = -1;
        for (int i = lane; i < P; i += 32) {
            unsigned long long kk = s_pkey[i];
            if (kk > cur) { cur = kk; curs = i; }
        }
        rounds = 0;
        #pragma unroll 1
        for (int k = 0; k < TOPK_; k++) {
            unsigned long long bk = cur;
            #pragma unroll
            for (int o = 16; o > 0; o >>= 1) {
                unsigned long long ok = __shfl_xor_sync(0xffffffffu, bk, o);
                if (ok > bk) bk = ok;
            }
            unsigned won = __ballot_sync(0xffffffffu, cur == bk);  // keys unique
            int bl = __ffs(won) - 1;
            if (lane == bl) {
                s_wkey[k] = bk; s_wov[k] = s_pov[curs];
                s_pkey[curs] = 0ull;
                cur = 0ull; curs = -1;
                for (int i = lane; i < P; i += 32) {
                    unsigned long long kk = s_pkey[i];
                    if (kk > cur) { cur = kk; curs = i; }
                }
            }
            rounds++;
        }
        __syncwarp();
        if (lane < rounds) {
            unsigned long long kk = s_wkey[lane];
            int n_w = (int)(0xFFFFFFFFu - (unsigned)(kk & 0xFFFFFFFFull));
            float alv = __uint_as_float((unsigned)(kk >> 32));
            emit_claim(base + n_w, g, alv, s_wov[lane]);
        }
    }

    // zero-pad: remaining winners = lowest-index zero-align anchors (global order)
    int Z = TOPK_ - rounds;
    if (Z > 0) {
        int cutoff = -1;
        if (lane == 0) {
            int cum = 0;
            #pragma unroll 1
            for (int w = 0; w < 16; w++) {
                unsigned z = ~s_bm[w];
                int c = __popc(z);
                if (cum + c >= Z) {
                    int need = Z - cum;
                    while (true) {
                        int bit = __ffs(z) - 1;
                        if (--need == 0) { cutoff = w*32 + bit; break; }
                        z &= z - 1;
                    }
                    break;
                }
                cum += c;
            }
        }
        cutoff = __shfl_sync(0xffffffffu, cutoff, 0);
        int Bc = min(s_bcnt, B_CAP);
        for (int i = lane; i < Bc; i += 32) {
            int n_w = s_bidx[i];
            if (n_w <= cutoff)
                emit_claim(base + n_w, g, 0.f, s_bov[i]);
        }
    }
}

// ---------------- K2: resolve + ALL dense outputs + fg>0 compaction ----------------
__global__ void __launch_bounds__(256) k2_resolve(
    const float* __restrict__ pd_scores, const float* __restrict__ pd_bboxes,
    const int* __restrict__ gt_labels,  const float* __restrict__ gt_bboxes,
    const float* __restrict__ mask_gt,  const float* __restrict__ gt_kkpts,
    const float* __restrict__ pd_kkpts, const float* __restrict__ sigma,
    const int* __restrict__ regmax_p,
    float* __restrict__ o_tlabels, float* __restrict__ o_tbboxes,
    float* __restrict__ o_fg, float* __restrict__ o_tgi,
    float* __restrict__ o_tscores)
{
    __shared__ GTC s_gt[NMAX];
    int b = blockIdx.y;
    int tid = threadIdx.x;
    int nbase = blockIdx.x * 256;
    int n = nbase + tid;
    bool active = (n < NA);
    size_t i = (size_t)b * NA + (active ? n : 0);

    unsigned c = 0u;
    if (active) { c = g_cnt[i]; g_cnt[i] = 0u; }   // reset for next graph replay
    float fg = 0.f, al = 0.f, ovown = 0.f;
    int owner = 0;

    if (active && c == 1u) {
        uint4 cl = g_claim[i];
        owner = (int)cl.x;
        al    = __uint_as_float(cl.y);
        ovown = __uint_as_float(cl.z);
        fg = 1.f;
    }

    bool multi = active && (c > 1u);
    if (__syncthreads_or((int)multi)) {
        if (tid < NMAX) make_gtc(s_gt[tid], gt_bboxes, gt_labels, mask_gt, gt_kkpts, b*NMAX + tid);
        __syncthreads();
        if (multi) {
            float rmf = parse_rmf(regmax_p);
            float rmscale = (rmf - 1.f) * 2.f;
            float sg = sigma[0];
            float fs2 = (2.f*sg)*(2.f*sg);
            float ax, ay, aps;
            anchor_decode(n, rmscale, ax, ay, aps);
            float4 box = ((const float4*)pd_bboxes)[i];
            float atn = pd_atan(box);
            float pkx = pd_kkpts[i*3], pky = pd_kkpts[i*3+1];
            float bv = -1.f; int bgi = 0;
            for (int gg = 0; gg < NMAX; gg++) {
                const GTC& gc = s_gt[gg];
                float ov = 0.f;
                if (gc.valid != 0.f) {
                    float din = fminf(fminf(ax - gc.gx1, ay - gc.gy1),
                                      fminf(gc.gx2 - ax, gc.gy2 - ay));
                    if ((din > EPS) && ((aps - gc.gt_size) >= EPS))
                        ov = eval_overlap(gc, box, atn, pkx, pky, fs2);
                }
                if (ov > bv) { bv = ov; bgi = gg; }
            }
            owner = bgi; ovown = bv; fg = 1.f;
            const GTC& go = s_gt[owner];
            float din = fminf(fminf(ax - go.gx1, ay - go.gy1),
                              fminf(go.gx2 - ax, go.gy2 - ay));
            float m = ((go.valid != 0.f) && (din > EPS) && ((aps - go.gt_size) >= EPS)) ? 1.f : 0.f;
            float score = pd_scores[i * NC + go.lbl] * m;
            al = score * powf(ovown, 6.0f);
            if (al < FLT_MIN_NORMAL) al = 0.f;
        }
    }

    // per-anchor dense outputs (everything except the one-hot tscores value)
    if (active) {
        int lbl = __ldg(&gt_labels[b * NMAX + owner]); if (lbl < 0) lbl = 0;
        o_tlabels[i] = (float)lbl;
        ((float4*)o_tbboxes)[i] = __ldg(&((const float4*)gt_bboxes)[b * NMAX + owner]);
        o_fg[i]  = fg;
        o_tgi[i] = (float)owner;
        if (fg > 0.f) {
            atomicMax(&g_posalign[b*NMAX + owner], __float_as_uint(al));
            atomicMax(&g_posov   [b*NMAX + owner], __float_as_uint(ovown));
            int slot = atomicAdd(&g_poscnt, 1);
            if (slot < POS_MAX)
                g_poslist[slot] = make_uint4((unsigned)i, (unsigned)(b*NMAX + owner),
                                             __float_as_uint(al), (unsigned)lbl);
        }
    }

    // uniform zero-fill of this block's tscores slice (k3 scatters the one-hots)
    int cnt = min(256, NA - nbase);
    if (cnt > 0) {
        float4* outp = (float4*)(o_tscores + ((size_t)b * NA + nbase) * NC);
        int tot4 = cnt * 20;
        float4 zv = make_float4(0.f, 0.f, 0.f, 0.f);
        for (int f = tid; f < tot4; f += 256) outp[f] = zv;
    }
}

// ---------------- K3: sparse one-hot scatter (<=13312 entries) ----------------
__global__ void __launch_bounds__(256) k3_scatter(float* __restrict__ o_tscores)
{
    int j = blockIdx.x * 256 + threadIdx.x;
    if (j >= g_poscnt) return;
    uint4 e = g_poslist[j];
    float al = __uint_as_float(e.z);
    float po = __uint_as_float(g_posov[e.y]);
    float pa = __uint_as_float(g_posalign[e.y]);
    float val = al * po / (pa + EPS);
    o_tscores[(size_t)e.x * NC + e.w] = val;
}

// ---------------- host ----------------
extern "C" void kernel_launch(void* const* d_in, const int* in_sizes, int n_in,
                              void* d_out, int out_size)
{
    const float* pd_scores = (const float*)d_in[0];
    const float* pd_bboxes = (const float*)d_in[1];
    const int*   gt_labels = (const int*)  d_in[3];
    const float* gt_bboxes = (const float*)d_in[4];
    const float* mask_gt   = (const float*)d_in[5];
    const float* gt_kkpts  = (const float*)d_in[6];
    const float* pd_kkpts  = (const float*)d_in[7];
    const float* sigma     = (const float*)d_in[8];
    const int*   regmax    = (n_in > 10) ? (const int*)d_in[10] : nullptr;

    float* out       = (float*)d_out;
    float* o_tlabels = out;
    float* o_tbboxes = out + (size_t)BS*NA;
    float* o_tscores = out + (size_t)BS*NA*5;
    float* o_fg      = out + (size_t)BS*NA*(5 + NC);
    float* o_tgi     = out + (size_t)BS*NA*(6 + NC);

    k1_metrics<<<BS*NMAX, NT1>>>(pd_scores, pd_bboxes, gt_labels, gt_bboxes,
                                 mask_gt, gt_kkpts, pd_kkpts, sigma, regmax);
    {
        dim3 grid((NA + 255)/256, BS);
        k2_resolve<<<grid, 256>>>(pd_scores, pd_bboxes, gt_labels, gt_bboxes,
                                  mask_gt, gt_kkpts, pd_kkpts, sigma, regmax,
                                  o_tlabels, o_tbboxes, o_fg, o_tgi, o_tscores);
    }
    k3_scatter<<<POS_MAX/256, 256>>>(o_tscores);
}